// round 3
// baseline (speedup 1.0000x reference)
#include <cuda_runtime.h>
#include <cuda_bf16.h>
#include <math_constants.h>

// Problem constants
#define BSZ 4
#define SEQ 1024
#define TOK (BSZ * SEQ)          // 4096
#define DMODEL 2048
#define NHEADS 32
#define NKV 8
#define HDIM 64
#define GROUPS (NHEADS / NKV)     // 4
#define KVDIM (NKV * HDIM)        // 512
#define ATTN_SCALE 0.125f         // 64^-0.5

// ---------------- scratch (static device globals; no allocation) ----------
__device__ float g_Q[(size_t)TOK * DMODEL];     // [T, 32, 64]
__device__ float g_K[(size_t)TOK * KVDIM];      // [T, 8, 64]
__device__ float g_V[(size_t)TOK * KVDIM];      // [T, 8, 64]
__device__ float g_attn[(size_t)TOK * DMODEL];  // [T, 32, 64]

// ---------------- simple tiled fp32 GEMM: C[M,N] = A[M,K] @ B[K,N] --------
// M % 64 == 0, N % 64 == 0, K % 16 == 0 (holds for all four GEMMs here).
#define GBM 64
#define GBN 64
#define GBK 16

__global__ __launch_bounds__(256) void gemm_f32(
    const float* __restrict__ A, const float* __restrict__ B,
    float* __restrict__ C, int M, int N, int K)
{
    __shared__ float As[GBK][GBM];      // transposed A tile
    __shared__ float Bs[GBK][GBN];

    const int tid  = threadIdx.x;
    const int tx   = tid & 15;          // 0..15 -> 4 cols each
    const int ty   = tid >> 4;          // 0..15 -> 4 rows each
    const int brow = blockIdx.y * GBM;
    const int bcol = blockIdx.x * GBN;

    const int l  = tid * 4;
    const int ar = l >> 4, ac = l & 15;     // A tile coords (64x16)
    const int br = l >> 6, bc = l & 63;     // B tile coords (16x64)

    float acc[4][4];
#pragma unroll
    for (int i = 0; i < 4; i++)
#pragma unroll
        for (int j = 0; j < 4; j++) acc[i][j] = 0.f;

    for (int k0 = 0; k0 < K; k0 += GBK) {
        float4 av = *reinterpret_cast<const float4*>(
            A + (size_t)(brow + ar) * K + k0 + ac);
        As[ac + 0][ar] = av.x;
        As[ac + 1][ar] = av.y;
        As[ac + 2][ar] = av.z;
        As[ac + 3][ar] = av.w;

        float4 bv = *reinterpret_cast<const float4*>(
            B + (size_t)(k0 + br) * N + bcol + bc);
        *reinterpret_cast<float4*>(&Bs[br][bc]) = bv;

        __syncthreads();

#pragma unroll
        for (int kk = 0; kk < GBK; kk++) {
            float a[4], b[4];
#pragma unroll
            for (int i = 0; i < 4; i++) a[i] = As[kk][ty * 4 + i];
#pragma unroll
            for (int j = 0; j < 4; j++) b[j] = Bs[kk][tx * 4 + j];
#pragma unroll
            for (int i = 0; i < 4; i++)
#pragma unroll
                for (int j = 0; j < 4; j++)
                    acc[i][j] = fmaf(a[i], b[j], acc[i][j]);
        }
        __syncthreads();
    }

#pragma unroll
    for (int i = 0; i < 4; i++) {
        float4 v = make_float4(acc[i][0], acc[i][1], acc[i][2], acc[i][3]);
        *reinterpret_cast<float4*>(
            C + (size_t)(brow + ty * 4 + i) * N + bcol + tx * 4) = v;
    }
}

// ---------------- RoPE (in place) ------------------------------------------
// x: [T, H, 64]; cos/sin: [T, 32]. Rotate-half convention:
// out[i]    = x[i]   * c - x[i+32] * s
// out[i+32] = x[i+32]* c + x[i]    * s
__global__ void rope_kernel(float* __restrict__ x,
                            const float* __restrict__ cs,
                            const float* __restrict__ sn,
                            int H)
{
    int idx = blockIdx.x * blockDim.x + threadIdx.x;
    int total = TOK * H * 32;
    if (idx >= total) return;
    int i = idx & 31;
    int h = (idx >> 5) % H;
    int t = idx / (32 * H);
    float c = cs[t * 32 + i];
    float s = sn[t * 32 + i];
    float* p = x + (size_t)t * (H * HDIM) + h * HDIM;
    float x1 = p[i], x2 = p[i + 32];
    p[i]      = x1 * c - x2 * s;
    p[i + 32] = x2 * c + x1 * s;
}

// ---------------- causal GQA flash attention -------------------------------
// One block = 64 query rows of one (b, h). 64 threads, 1 row each.
// K/V tiles of 32 rows staged in shared memory; online softmax in registers.
#define FM 64
#define FN 32

__global__ __launch_bounds__(64) void flash_kernel(
    const float* __restrict__ Q, const float* __restrict__ K,
    const float* __restrict__ V, float* __restrict__ O)
{
    const int qt  = blockIdx.x;           // 0..15
    const int h   = blockIdx.y;           // 0..31
    const int b   = blockIdx.z;           // 0..3
    const int kvh = h / GROUPS;
    const int tid = threadIdx.x;          // 0..63

    const int qi = qt * FM + tid;         // row within sequence
    const int t  = b * SEQ + qi;          // token index

    __shared__ float Ks[FN][HDIM];
    __shared__ float Vs[FN][HDIM];

    float q[HDIM];
    const float* qp = Q + (size_t)t * DMODEL + h * HDIM;
#pragma unroll
    for (int d = 0; d < HDIM; d++) q[d] = qp[d] * ATTN_SCALE;

    float acc[HDIM];
#pragma unroll
    for (int d = 0; d < HDIM; d++) acc[d] = 0.f;
    float m = -CUDART_INF_F;
    float lsum = 0.f;

    const int kend = qt * FM + FM;        // exclusive upper bound of keys
    for (int kb = 0; kb < kend; kb += FN) {
        // stage K/V tile (coalesced; 32 floats per thread per tensor)
        for (int idx = tid; idx < FN * HDIM; idx += 64) {
            int j = idx >> 6;
            int d = idx & 63;
            int tk = b * SEQ + kb + j;
            Ks[j][d] = K[(size_t)tk * KVDIM + kvh * HDIM + d];
            Vs[j][d] = V[(size_t)tk * KVDIM + kvh * HDIM + d];
        }
        __syncthreads();

        float s[FN];
        float mb = -CUDART_INF_F;
#pragma unroll
        for (int j = 0; j < FN; j++) {
            // 4-way split accumulation for ILP
            float d0 = 0.f, d1 = 0.f, d2 = 0.f, d3 = 0.f;
#pragma unroll
            for (int d = 0; d < HDIM; d += 4) {
                d0 = fmaf(q[d + 0], Ks[j][d + 0], d0);
                d1 = fmaf(q[d + 1], Ks[j][d + 1], d1);
                d2 = fmaf(q[d + 2], Ks[j][d + 2], d2);
                d3 = fmaf(q[d + 3], Ks[j][d + 3], d3);
            }
            float dot = (d0 + d1) + (d2 + d3);
            s[j] = (kb + j <= qi) ? dot : -CUDART_INF_F;
            mb = fmaxf(mb, s[j]);
        }

        float mn = fmaxf(m, mb);
        float sf = __expf(m - mn);        // m=-inf first iter -> sf=0 (mn finite)
        lsum *= sf;
#pragma unroll
        for (int d = 0; d < HDIM; d++) acc[d] *= sf;

#pragma unroll
        for (int j = 0; j < FN; j++) {
            float p = __expf(s[j] - mn);  // masked -> exp(-inf)=0
            lsum += p;
#pragma unroll
            for (int d = 0; d < HDIM; d++)
                acc[d] = fmaf(p, Vs[j][d], acc[d]);
        }
        m = mn;
        __syncthreads();
    }

    float inv = 1.0f / lsum;
    float* op = O + (size_t)t * DMODEL + h * HDIM;
#pragma unroll
    for (int d = 0; d < HDIM; d++) op[d] = acc[d] * inv;
}

// ---------------- launch ----------------------------------------------------
extern "C" void kernel_launch(void* const* d_in, const int* in_sizes, int n_in,
                              void* d_out, int out_size)
{
    const float* hidden = (const float*)d_in[0];   // [T, 2048]
    const float* cs     = (const float*)d_in[1];   // [T, 32]
    const float* sn     = (const float*)d_in[2];   // [T, 32]
    const float* Wq     = (const float*)d_in[3];   // [2048, 2048]
    const float* Wk     = (const float*)d_in[4];   // [2048, 512]
    const float* Wv     = (const float*)d_in[5];   // [2048, 512]
    const float* Wo     = (const float*)d_in[6];   // [2048, 2048]
    float* out          = (float*)d_out;           // [T, 2048]

    float* Q  = nullptr; cudaGetSymbolAddress((void**)&Q,  g_Q);
    float* Kp = nullptr; cudaGetSymbolAddress((void**)&Kp, g_K);
    float* Vp = nullptr; cudaGetSymbolAddress((void**)&Vp, g_V);
    float* At = nullptr; cudaGetSymbolAddress((void**)&At, g_attn);

    dim3 gq(DMODEL / GBN, TOK / GBM);
    dim3 gkv(KVDIM / GBN, TOK / GBM);

    // Projections
    gemm_f32<<<gq, 256>>>(hidden, Wq, Q, TOK, DMODEL, DMODEL);
    gemm_f32<<<gkv, 256>>>(hidden, Wk, Kp, TOK, KVDIM, DMODEL);
    gemm_f32<<<gkv, 256>>>(hidden, Wv, Vp, TOK, KVDIM, DMODEL);

    // RoPE on q and k
    {
        int totq = TOK * NHEADS * 32;
        rope_kernel<<<(totq + 255) / 256, 256>>>(Q, cs, sn, NHEADS);
        int totk = TOK * NKV * 32;
        rope_kernel<<<(totk + 255) / 256, 256>>>(Kp, cs, sn, NKV);
    }

    // Attention
    {
        dim3 grid(SEQ / FM, NHEADS, BSZ);
        flash_kernel<<<grid, 64>>>(Q, Kp, Vp, At);
    }

    // Output projection
    gemm_f32<<<gq, 256>>>(At, Wo, out, TOK, DMODEL, DMODEL);
}

// round 4
// speedup vs baseline: 1.0005x; 1.0005x over previous
#include <cuda_runtime.h>
#include <cuda_bf16.h>
#include <math_constants.h>

// Problem constants
#define BSZ 4
#define SEQ 1024
#define TOK (BSZ * SEQ)          // 4096
#define DMODEL 2048
#define NHEADS 32
#define NKV 8
#define HDIM 64
#define GROUPS (NHEADS / NKV)     // 4
#define KVDIM (NKV * HDIM)        // 512
#define ATTN_SCALE 0.125f         // 64^-0.5

// ---------------- scratch (static device globals; no allocation) ----------
__device__ float g_Q[(size_t)TOK * DMODEL];     // [T, 32, 64]
__device__ float g_K[(size_t)TOK * KVDIM];      // [T, 8, 64]
__device__ float g_V[(size_t)TOK * KVDIM];      // [T, 8, 64]
__device__ float g_attn[(size_t)TOK * DMODEL];  // [T, 32, 64]

// ---------------- simple tiled fp32 GEMM: C[M,N] = A[M,K] @ B[K,N] --------
// M % 64 == 0, N % 64 == 0, K % 16 == 0 (holds for all four GEMMs here).
#define GBM 64
#define GBN 64
#define GBK 16

__global__ __launch_bounds__(256) void gemm_f32(
    const float* __restrict__ A, const float* __restrict__ B,
    float* __restrict__ C, int M, int N, int K)
{
    __shared__ float As[GBK][GBM];      // transposed A tile
    __shared__ float Bs[GBK][GBN];

    const int tid  = threadIdx.x;
    const int tx   = tid & 15;          // 0..15 -> 4 cols each
    const int ty   = tid >> 4;          // 0..15 -> 4 rows each
    const int brow = blockIdx.y * GBM;
    const int bcol = blockIdx.x * GBN;

    const int l  = tid * 4;
    const int ar = l >> 4, ac = l & 15;     // A tile coords (64x16)
    const int br = l >> 6, bc = l & 63;     // B tile coords (16x64)

    float acc[4][4];
#pragma unroll
    for (int i = 0; i < 4; i++)
#pragma unroll
        for (int j = 0; j < 4; j++) acc[i][j] = 0.f;

    for (int k0 = 0; k0 < K; k0 += GBK) {
        float4 av = *reinterpret_cast<const float4*>(
            A + (size_t)(brow + ar) * K + k0 + ac);
        As[ac + 0][ar] = av.x;
        As[ac + 1][ar] = av.y;
        As[ac + 2][ar] = av.z;
        As[ac + 3][ar] = av.w;

        float4 bv = *reinterpret_cast<const float4*>(
            B + (size_t)(k0 + br) * N + bcol + bc);
        *reinterpret_cast<float4*>(&Bs[br][bc]) = bv;

        __syncthreads();

#pragma unroll
        for (int kk = 0; kk < GBK; kk++) {
            float a[4], b[4];
#pragma unroll
            for (int i = 0; i < 4; i++) a[i] = As[kk][ty * 4 + i];
#pragma unroll
            for (int j = 0; j < 4; j++) b[j] = Bs[kk][tx * 4 + j];
#pragma unroll
            for (int i = 0; i < 4; i++)
#pragma unroll
                for (int j = 0; j < 4; j++)
                    acc[i][j] = fmaf(a[i], b[j], acc[i][j]);
        }
        __syncthreads();
    }

#pragma unroll
    for (int i = 0; i < 4; i++) {
        float4 v = make_float4(acc[i][0], acc[i][1], acc[i][2], acc[i][3]);
        *reinterpret_cast<float4*>(
            C + (size_t)(brow + ty * 4 + i) * N + bcol + tx * 4) = v;
    }
}

// ---------------- RoPE (in place) ------------------------------------------
// x: [T, H, 64]; cos/sin: [T, 32]. Rotate-half convention:
// out[i]    = x[i]   * c - x[i+32] * s
// out[i+32] = x[i+32]* c + x[i]    * s
__global__ void rope_kernel(float* __restrict__ x,
                            const float* __restrict__ cs,
                            const float* __restrict__ sn,
                            int H)
{
    int idx = blockIdx.x * blockDim.x + threadIdx.x;
    int total = TOK * H * 32;
    if (idx >= total) return;
    int i = idx & 31;
    int h = (idx >> 5) % H;
    int t = idx / (32 * H);
    float c = cs[t * 32 + i];
    float s = sn[t * 32 + i];
    float* p = x + (size_t)t * (H * HDIM) + h * HDIM;
    float x1 = p[i], x2 = p[i + 32];
    p[i]      = x1 * c - x2 * s;
    p[i + 32] = x2 * c + x1 * s;
}

// ---------------- causal GQA flash attention -------------------------------
// One block = 64 query rows of one (b, h). 64 threads, 1 row each.
// K/V tiles of 32 rows staged in shared memory; online softmax in registers.
#define FM 64
#define FN 32

__global__ __launch_bounds__(64) void flash_kernel(
    const float* __restrict__ Q, const float* __restrict__ K,
    const float* __restrict__ V, float* __restrict__ O)
{
    const int qt  = blockIdx.x;           // 0..15
    const int h   = blockIdx.y;           // 0..31
    const int b   = blockIdx.z;           // 0..3
    const int kvh = h / GROUPS;
    const int tid = threadIdx.x;          // 0..63

    const int qi = qt * FM + tid;         // row within sequence
    const int t  = b * SEQ + qi;          // token index

    __shared__ float Ks[FN][HDIM];
    __shared__ float Vs[FN][HDIM];

    float q[HDIM];
    const float* qp = Q + (size_t)t * DMODEL + h * HDIM;
#pragma unroll
    for (int d = 0; d < HDIM; d++) q[d] = qp[d] * ATTN_SCALE;

    float acc[HDIM];
#pragma unroll
    for (int d = 0; d < HDIM; d++) acc[d] = 0.f;
    float m = -CUDART_INF_F;
    float lsum = 0.f;

    const int kend = qt * FM + FM;        // exclusive upper bound of keys
    for (int kb = 0; kb < kend; kb += FN) {
        // stage K/V tile (coalesced; 32 floats per thread per tensor)
        for (int idx = tid; idx < FN * HDIM; idx += 64) {
            int j = idx >> 6;
            int d = idx & 63;
            int tk = b * SEQ + kb + j;
            Ks[j][d] = K[(size_t)tk * KVDIM + kvh * HDIM + d];
            Vs[j][d] = V[(size_t)tk * KVDIM + kvh * HDIM + d];
        }
        __syncthreads();

        float s[FN];
        float mb = -CUDART_INF_F;
#pragma unroll
        for (int j = 0; j < FN; j++) {
            // 4-way split accumulation for ILP
            float d0 = 0.f, d1 = 0.f, d2 = 0.f, d3 = 0.f;
#pragma unroll
            for (int d = 0; d < HDIM; d += 4) {
                d0 = fmaf(q[d + 0], Ks[j][d + 0], d0);
                d1 = fmaf(q[d + 1], Ks[j][d + 1], d1);
                d2 = fmaf(q[d + 2], Ks[j][d + 2], d2);
                d3 = fmaf(q[d + 3], Ks[j][d + 3], d3);
            }
            float dot = (d0 + d1) + (d2 + d3);
            s[j] = (kb + j <= qi) ? dot : -CUDART_INF_F;
            mb = fmaxf(mb, s[j]);
        }

        float mn = fmaxf(m, mb);
        float sf = __expf(m - mn);        // m=-inf first iter -> sf=0 (mn finite)
        lsum *= sf;
#pragma unroll
        for (int d = 0; d < HDIM; d++) acc[d] *= sf;

#pragma unroll
        for (int j = 0; j < FN; j++) {
            float p = __expf(s[j] - mn);  // masked -> exp(-inf)=0
            lsum += p;
#pragma unroll
            for (int d = 0; d < HDIM; d++)
                acc[d] = fmaf(p, Vs[j][d], acc[d]);
        }
        m = mn;
        __syncthreads();
    }

    float inv = 1.0f / lsum;
    float* op = O + (size_t)t * DMODEL + h * HDIM;
#pragma unroll
    for (int d = 0; d < HDIM; d++) op[d] = acc[d] * inv;
}

// ---------------- launch ----------------------------------------------------
extern "C" void kernel_launch(void* const* d_in, const int* in_sizes, int n_in,
                              void* d_out, int out_size)
{
    const float* hidden = (const float*)d_in[0];   // [T, 2048]
    const float* cs     = (const float*)d_in[1];   // [T, 32]
    const float* sn     = (const float*)d_in[2];   // [T, 32]
    const float* Wq     = (const float*)d_in[3];   // [2048, 2048]
    const float* Wk     = (const float*)d_in[4];   // [2048, 512]
    const float* Wv     = (const float*)d_in[5];   // [2048, 512]
    const float* Wo     = (const float*)d_in[6];   // [2048, 2048]
    float* out          = (float*)d_out;           // [T, 2048]

    float* Q  = nullptr; cudaGetSymbolAddress((void**)&Q,  g_Q);
    float* Kp = nullptr; cudaGetSymbolAddress((void**)&Kp, g_K);
    float* Vp = nullptr; cudaGetSymbolAddress((void**)&Vp, g_V);
    float* At = nullptr; cudaGetSymbolAddress((void**)&At, g_attn);

    dim3 gq(DMODEL / GBN, TOK / GBM);
    dim3 gkv(KVDIM / GBN, TOK / GBM);

    // Projections
    gemm_f32<<<gq, 256>>>(hidden, Wq, Q, TOK, DMODEL, DMODEL);
    gemm_f32<<<gkv, 256>>>(hidden, Wk, Kp, TOK, KVDIM, DMODEL);
    gemm_f32<<<gkv, 256>>>(hidden, Wv, Vp, TOK, KVDIM, DMODEL);

    // RoPE on q and k
    {
        int totq = TOK * NHEADS * 32;
        rope_kernel<<<(totq + 255) / 256, 256>>>(Q, cs, sn, NHEADS);
        int totk = TOK * NKV * 32;
        rope_kernel<<<(totk + 255) / 256, 256>>>(Kp, cs, sn, NKV);
    }

    // Attention
    {
        dim3 grid(SEQ / FM, NHEADS, BSZ);
        flash_kernel<<<grid, 64>>>(Q, Kp, Vp, At);
    }

    // Output projection
    gemm_f32<<<gq, 256>>>(At, Wo, out, TOK, DMODEL, DMODEL);
}

// round 6
// speedup vs baseline: 1.7432x; 1.7423x over previous
#include <cuda_runtime.h>
#include <cuda_bf16.h>
#include <cstdint>
#include <math_constants.h>

// Problem constants
#define BSZ 4
#define SEQ 1024
#define TOK (BSZ * SEQ)          // 4096
#define DMODEL 2048
#define NHEADS 32
#define NKV 8
#define HDIM 64
#define GROUPS (NHEADS / NKV)     // 4
#define KVDIM (NKV * HDIM)        // 512
#define ATTN_SCALE 0.125f         // 64^-0.5

// ---------------- scratch (static device globals; no allocation) ----------
__device__ float g_Q[(size_t)TOK * DMODEL];
__device__ float g_K[(size_t)TOK * KVDIM];
__device__ float g_V[(size_t)TOK * KVDIM];
__device__ float g_attn[(size_t)TOK * DMODEL];
__device__ __align__(16) __nv_bfloat16 g_Ahi[(size_t)TOK * DMODEL];
__device__ __align__(16) __nv_bfloat16 g_Alo[(size_t)TOK * DMODEL];
__device__ __align__(16) __nv_bfloat16 g_Bhi[(size_t)DMODEL * DMODEL];  // [N,K]
__device__ __align__(16) __nv_bfloat16 g_Blo[(size_t)DMODEL * DMODEL];

// =================== PTX helpers (compute_103-safe, sm_80-era) =============
__device__ __forceinline__ uint32_t smem_u32(const void* p) {
    uint32_t a;
    asm("{ .reg .u64 t; cvta.to.shared.u64 t, %1; cvt.u32.u64 %0, t; }"
        : "=r"(a) : "l"(p));
    return a;
}

#define CP_ASYNC16(dst, src) \
    asm volatile("cp.async.cg.shared.global [%0], [%1], 16;" \
                 :: "r"(dst), "l"(src) : "memory")
#define CP_COMMIT() asm volatile("cp.async.commit_group;" ::: "memory")
#define CP_WAIT1()  asm volatile("cp.async.wait_group 1;" ::: "memory")
#define CP_WAIT0()  asm volatile("cp.async.wait_group 0;" ::: "memory")

#define LDMATRIX_X4(r0, r1, r2, r3, addr) \
    asm volatile("ldmatrix.sync.aligned.m8n8.x4.shared.b16 {%0,%1,%2,%3}, [%4];" \
                 : "=r"(r0), "=r"(r1), "=r"(r2), "=r"(r3) : "r"(addr))

#define MMA16816(d, a, b) \
    asm volatile("mma.sync.aligned.m16n8k16.row.col.f32.bf16.bf16.f32 " \
                 "{%0,%1,%2,%3}, {%4,%5,%6,%7}, {%8,%9}, {%0,%1,%2,%3};" \
                 : "+f"((d)[0]), "+f"((d)[1]), "+f"((d)[2]), "+f"((d)[3]) \
                 : "r"((a)[0]), "r"((a)[1]), "r"((a)[2]), "r"((a)[3]), \
                   "r"((b)[0]), "r"((b)[1]))

// =================== conversion kernels =====================================
__global__ void split_kernel(const float* __restrict__ A,
                             __nv_bfloat162* __restrict__ H,
                             __nv_bfloat162* __restrict__ L, int n4)
{
    int i = blockIdx.x * blockDim.x + threadIdx.x;
    if (i >= n4) return;
    float4 v = reinterpret_cast<const float4*>(A)[i];
    __nv_bfloat16 h0 = __float2bfloat16(v.x);
    __nv_bfloat16 h1 = __float2bfloat16(v.y);
    __nv_bfloat16 h2 = __float2bfloat16(v.z);
    __nv_bfloat16 h3 = __float2bfloat16(v.w);
    __nv_bfloat16 l0 = __float2bfloat16(v.x - __bfloat162float(h0));
    __nv_bfloat16 l1 = __float2bfloat16(v.y - __bfloat162float(h1));
    __nv_bfloat16 l2 = __float2bfloat16(v.z - __bfloat162float(h2));
    __nv_bfloat16 l3 = __float2bfloat16(v.w - __bfloat162float(h3));
    H[2 * i]     = __nv_bfloat162(h0, h1);
    H[2 * i + 1] = __nv_bfloat162(h2, h3);
    L[2 * i]     = __nv_bfloat162(l0, l1);
    L[2 * i + 1] = __nv_bfloat162(l2, l3);
}

// W [2048, N] row-major -> Th/Tl [N, 2048] transposed + bf16 hi/lo split.
__global__ void transpose_split(const float* __restrict__ W,
                                __nv_bfloat16* __restrict__ Th,
                                __nv_bfloat16* __restrict__ Tl, int N)
{
    __shared__ float tile[32][33];
    int n = blockIdx.x * 32 + threadIdx.x;
    int k = blockIdx.y * 32 + threadIdx.y;
#pragma unroll
    for (int j = 0; j < 32; j += 8)
        tile[threadIdx.y + j][threadIdx.x] = W[(size_t)(k + j) * N + n];
    __syncthreads();
    int k2 = blockIdx.y * 32 + threadIdx.x;
    int n2 = blockIdx.x * 32 + threadIdx.y;
#pragma unroll
    for (int j = 0; j < 32; j += 8) {
        float v = tile[threadIdx.x][threadIdx.y + j];
        __nv_bfloat16 h = __float2bfloat16(v);
        Th[(size_t)(n2 + j) * DMODEL + k2] = h;
        Tl[(size_t)(n2 + j) * DMODEL + k2] =
            __float2bfloat16(v - __bfloat162float(h));
    }
}

// =================== HMMA GEMM ==============================================
// C[M,N] = A[M,2048] @ W[2048,N]; A hi/lo [M,K] K-major, B hi/lo [N,K] K-major.
// CTA tile 128x128, BK=32 bf16, 2-stage cp.async pipeline.
// 8 warps as 2(m) x 4(n); warp tile 64x32 -> 4 m-tiles(16) x 4 n-tiles(8).
// acc += Ah*Bh + Ah*Bl + Al*Bh.

#define BM 128
#define BN 128
#define BK 32
#define TILE_B (128 * BK * 2)          // 8192 B per tensor tile
#define STAGE_B (4 * TILE_B)           // 32768
#define GEMM_SMEM (2 * STAGE_B)        // 65536

// swizzle: 4 16B-chunks per 64B row; chunk' = chunk ^ (row & 3)
__device__ __forceinline__ uint32_t sw_off(int row, int c16) {
    return (uint32_t)(row * 64 + ((c16 ^ (row & 3)) * 16));
}

__device__ __forceinline__ void stage_load(
    const __nv_bfloat16* __restrict__ aH, const __nv_bfloat16* __restrict__ aL,
    const __nv_bfloat16* __restrict__ bH, const __nv_bfloat16* __restrict__ bL,
    uint32_t sbase, int k0, int tid)
{
#pragma unroll
    for (int j = 0; j < 2; j++) {
        int i = tid + j * 256;
        int row = i >> 2;
        int c16 = i & 3;
        uint32_t doff = sw_off(row, c16);
        size_t goff = (size_t)row * DMODEL + k0 + c16 * 8;
        CP_ASYNC16(sbase + 0 * TILE_B + doff, aH + goff);
        CP_ASYNC16(sbase + 1 * TILE_B + doff, aL + goff);
        CP_ASYNC16(sbase + 2 * TILE_B + doff, bH + goff);
        CP_ASYNC16(sbase + 3 * TILE_B + doff, bL + goff);
    }
}

__global__ void __launch_bounds__(256, 1) gemm_mma(
    const __nv_bfloat16* __restrict__ Ahi, const __nv_bfloat16* __restrict__ Alo,
    const __nv_bfloat16* __restrict__ Bhi, const __nv_bfloat16* __restrict__ Blo,
    float* __restrict__ C, int N)
{
    extern __shared__ char smem[];
    uint32_t sb = smem_u32(smem);
    const int tid = threadIdx.x;
    const int lane = tid & 31;
    const int wid = tid >> 5;
    const int wm = wid >> 2;          // 0..1 -> 64 rows
    const int wn = wid & 3;           // 0..3 -> 32 cols
    const int brow = blockIdx.y * BM;
    const int bcol = blockIdx.x * BN;

    const __nv_bfloat16* aH = Ahi + (size_t)brow * DMODEL;
    const __nv_bfloat16* aL = Alo + (size_t)brow * DMODEL;
    const __nv_bfloat16* bH = Bhi + (size_t)bcol * DMODEL;
    const __nv_bfloat16* bL = Blo + (size_t)bcol * DMODEL;

    float acc[4][4][4];
#pragma unroll
    for (int i = 0; i < 4; i++)
#pragma unroll
        for (int j = 0; j < 4; j++)
#pragma unroll
            for (int q = 0; q < 4; q++) acc[i][j][q] = 0.f;

    const int NC = DMODEL / BK;       // 64
    stage_load(aH, aL, bH, bL, sb, 0, tid);
    CP_COMMIT();

    for (int c = 0; c < NC; c++) {
        uint32_t st = sb + (uint32_t)(c & 1) * STAGE_B;
        if (c + 1 < NC) {
            stage_load(aH, aL, bH, bL, sb + (uint32_t)((c + 1) & 1) * STAGE_B,
                       (c + 1) * BK, tid);
            CP_COMMIT();
            CP_WAIT1();
        } else {
            CP_WAIT0();
        }
        __syncthreads();

#pragma unroll
        for (int ks = 0; ks < 2; ks++) {
            // A fragments (hi & lo): 4 m-tiles
            uint32_t fAh[4][4], fAl[4][4];
#pragma unroll
            for (int mt = 0; mt < 4; mt++) {
                int row = wm * 64 + mt * 16 + (lane & 15);
                int c16 = ks * 2 + (lane >> 4);
                uint32_t off = sw_off(row, c16);
                LDMATRIX_X4(fAh[mt][0], fAh[mt][1], fAh[mt][2], fAh[mt][3],
                            st + 0 * TILE_B + off);
                LDMATRIX_X4(fAl[mt][0], fAl[mt][1], fAl[mt][2], fAl[mt][3],
                            st + 1 * TILE_B + off);
            }
            // B fragments: x4 load covers 2 n-tiles (k-lo, k-hi per tile)
            uint32_t fBh[4][2], fBl[4][2];
#pragma unroll
            for (int pr = 0; pr < 2; pr++) {
                int nrel = wn * 32 + pr * 16 + ((lane >> 4) * 8 + (lane & 7));
                int c16 = ks * 2 + ((lane >> 3) & 1);
                uint32_t off = sw_off(nrel, c16);
                LDMATRIX_X4(fBh[2 * pr][0], fBh[2 * pr][1],
                            fBh[2 * pr + 1][0], fBh[2 * pr + 1][1],
                            st + 2 * TILE_B + off);
                LDMATRIX_X4(fBl[2 * pr][0], fBl[2 * pr][1],
                            fBl[2 * pr + 1][0], fBl[2 * pr + 1][1],
                            st + 3 * TILE_B + off);
            }
#pragma unroll
            for (int mt = 0; mt < 4; mt++)
#pragma unroll
                for (int nt = 0; nt < 4; nt++) {
                    MMA16816(acc[mt][nt], fAh[mt], fBh[nt]);
                    MMA16816(acc[mt][nt], fAh[mt], fBl[nt]);
                    MMA16816(acc[mt][nt], fAl[mt], fBh[nt]);
                }
        }
        __syncthreads();
    }

    // epilogue: C frag layout m16n8: (row = lane>>2 [+8], col = (lane&3)*2 [+1])
#pragma unroll
    for (int mt = 0; mt < 4; mt++) {
#pragma unroll
        for (int nt = 0; nt < 4; nt++) {
            int m = brow + wm * 64 + mt * 16 + (lane >> 2);
            int n = bcol + wn * 32 + nt * 8 + (lane & 3) * 2;
            float2 v0 = make_float2(acc[mt][nt][0], acc[mt][nt][1]);
            float2 v1 = make_float2(acc[mt][nt][2], acc[mt][nt][3]);
            *reinterpret_cast<float2*>(C + (size_t)m * N + n) = v0;
            *reinterpret_cast<float2*>(C + (size_t)(m + 8) * N + n) = v1;
        }
    }
}

// ---------------- RoPE (in place) -------------------------------------------
__global__ void rope_kernel(float* __restrict__ x,
                            const float* __restrict__ cs,
                            const float* __restrict__ sn,
                            int H)
{
    int idx = blockIdx.x * blockDim.x + threadIdx.x;
    int total = TOK * H * 32;
    if (idx >= total) return;
    int i = idx & 31;
    int h = (idx >> 5) % H;
    int t = idx / (32 * H);
    float c = cs[t * 32 + i];
    float s = sn[t * 32 + i];
    float* p = x + (size_t)t * (H * HDIM) + h * HDIM;
    float x1 = p[i], x2 = p[i + 32];
    p[i]      = x1 * c - x2 * s;
    p[i + 32] = x2 * c + x1 * s;
}

// ---------------- causal GQA flash attention (verified R4 version) ----------
#define FM 64
#define FN 32

__global__ __launch_bounds__(64) void flash_kernel(
    const float* __restrict__ Q, const float* __restrict__ K,
    const float* __restrict__ V, float* __restrict__ O)
{
    const int qt  = blockIdx.x;
    const int h   = blockIdx.y;
    const int b   = blockIdx.z;
    const int kvh = h / GROUPS;
    const int tid = threadIdx.x;

    const int qi = qt * FM + tid;
    const int t  = b * SEQ + qi;

    __shared__ float Ks[FN][HDIM];
    __shared__ float Vs[FN][HDIM];

    float q[HDIM];
    const float* qp = Q + (size_t)t * DMODEL + h * HDIM;
#pragma unroll
    for (int d = 0; d < HDIM; d++) q[d] = qp[d] * ATTN_SCALE;

    float acc[HDIM];
#pragma unroll
    for (int d = 0; d < HDIM; d++) acc[d] = 0.f;
    float m = -CUDART_INF_F;
    float lsum = 0.f;

    const int kend = qt * FM + FM;
    for (int kb = 0; kb < kend; kb += FN) {
        for (int idx = tid; idx < FN * HDIM; idx += 64) {
            int j = idx >> 6;
            int d = idx & 63;
            int tk = b * SEQ + kb + j;
            Ks[j][d] = K[(size_t)tk * KVDIM + kvh * HDIM + d];
            Vs[j][d] = V[(size_t)tk * KVDIM + kvh * HDIM + d];
        }
        __syncthreads();

        float s[FN];
        float mb = -CUDART_INF_F;
#pragma unroll
        for (int j = 0; j < FN; j++) {
            float d0 = 0.f, d1 = 0.f, d2 = 0.f, d3 = 0.f;
#pragma unroll
            for (int d = 0; d < HDIM; d += 4) {
                d0 = fmaf(q[d + 0], Ks[j][d + 0], d0);
                d1 = fmaf(q[d + 1], Ks[j][d + 1], d1);
                d2 = fmaf(q[d + 2], Ks[j][d + 2], d2);
                d3 = fmaf(q[d + 3], Ks[j][d + 3], d3);
            }
            float dot = (d0 + d1) + (d2 + d3);
            s[j] = (kb + j <= qi) ? dot : -CUDART_INF_F;
            mb = fmaxf(mb, s[j]);
        }

        float mn = fmaxf(m, mb);
        float sf = __expf(m - mn);
        lsum *= sf;
#pragma unroll
        for (int d = 0; d < HDIM; d++) acc[d] *= sf;

#pragma unroll
        for (int j = 0; j < FN; j++) {
            float p = __expf(s[j] - mn);
            lsum += p;
#pragma unroll
            for (int d = 0; d < HDIM; d++)
                acc[d] = fmaf(p, Vs[j][d], acc[d]);
        }
        m = mn;
        __syncthreads();
    }

    float inv = 1.0f / lsum;
    float* op = O + (size_t)t * DMODEL + h * HDIM;
#pragma unroll
    for (int d = 0; d < HDIM; d++) op[d] = acc[d] * inv;
}

// ---------------- launch ----------------------------------------------------
extern "C" void kernel_launch(void* const* d_in, const int* in_sizes, int n_in,
                              void* d_out, int out_size)
{
    const float* hidden = (const float*)d_in[0];
    const float* cs     = (const float*)d_in[1];
    const float* sn     = (const float*)d_in[2];
    const float* Wq     = (const float*)d_in[3];
    const float* Wk     = (const float*)d_in[4];
    const float* Wv     = (const float*)d_in[5];
    const float* Wo     = (const float*)d_in[6];
    float* out          = (float*)d_out;

    float* Q  = nullptr; cudaGetSymbolAddress((void**)&Q,  g_Q);
    float* Kp = nullptr; cudaGetSymbolAddress((void**)&Kp, g_K);
    float* Vp = nullptr; cudaGetSymbolAddress((void**)&Vp, g_V);
    float* At = nullptr; cudaGetSymbolAddress((void**)&At, g_attn);
    __nv_bfloat16* Ah = nullptr; cudaGetSymbolAddress((void**)&Ah, g_Ahi);
    __nv_bfloat16* Al = nullptr; cudaGetSymbolAddress((void**)&Al, g_Alo);
    __nv_bfloat16* Bh = nullptr; cudaGetSymbolAddress((void**)&Bh, g_Bhi);
    __nv_bfloat16* Bl = nullptr; cudaGetSymbolAddress((void**)&Bl, g_Blo);

    static bool attr_set = false;
    if (!attr_set) {
        cudaFuncSetAttribute(gemm_mma, cudaFuncAttributeMaxDynamicSharedMemorySize,
                             GEMM_SMEM);
        attr_set = true;
    }

    const int n4 = TOK * DMODEL / 4;

    // split hidden -> bf16 hi/lo
    split_kernel<<<n4 / 256, 256>>>(hidden, (__nv_bfloat162*)Ah,
                                    (__nv_bfloat162*)Al, n4);

    // Q = hidden @ Wq
    transpose_split<<<dim3(DMODEL / 32, DMODEL / 32), dim3(32, 8)>>>(Wq, Bh, Bl, DMODEL);
    gemm_mma<<<dim3(DMODEL / BN, TOK / BM), 256, GEMM_SMEM>>>(Ah, Al, Bh, Bl, Q, DMODEL);

    // K = hidden @ Wk
    transpose_split<<<dim3(KVDIM / 32, DMODEL / 32), dim3(32, 8)>>>(Wk, Bh, Bl, KVDIM);
    gemm_mma<<<dim3(KVDIM / BN, TOK / BM), 256, GEMM_SMEM>>>(Ah, Al, Bh, Bl, Kp, KVDIM);

    // V = hidden @ Wv
    transpose_split<<<dim3(KVDIM / 32, DMODEL / 32), dim3(32, 8)>>>(Wv, Bh, Bl, KVDIM);
    gemm_mma<<<dim3(KVDIM / BN, TOK / BM), 256, GEMM_SMEM>>>(Ah, Al, Bh, Bl, Vp, KVDIM);

    // RoPE on q and k
    {
        int totq = TOK * NHEADS * 32;
        rope_kernel<<<(totq + 255) / 256, 256>>>(Q, cs, sn, NHEADS);
        int totk = TOK * NKV * 32;
        rope_kernel<<<(totk + 255) / 256, 256>>>(Kp, cs, sn, NKV);
    }

    // Attention
    {
        dim3 grid(SEQ / FM, NHEADS, BSZ);
        flash_kernel<<<grid, 64>>>(Q, Kp, Vp, At);
    }

    // out = attn @ Wo
    split_kernel<<<n4 / 256, 256>>>(At, (__nv_bfloat162*)Ah, (__nv_bfloat162*)Al, n4);
    transpose_split<<<dim3(DMODEL / 32, DMODEL / 32), dim3(32, 8)>>>(Wo, Bh, Bl, DMODEL);
    gemm_mma<<<dim3(DMODEL / BN, TOK / BM), 256, GEMM_SMEM>>>(Ah, Al, Bh, Bl, out, DMODEL);
}

// round 7
// speedup vs baseline: 3.1450x; 1.8042x over previous
#include <cuda_runtime.h>
#include <cuda_bf16.h>
#include <cstdint>
#include <math_constants.h>

// Problem constants
#define BSZ 4
#define SEQ 1024
#define TOK (BSZ * SEQ)          // 4096
#define DMODEL 2048
#define NHEADS 32
#define NKV 8
#define HDIM 64
#define GROUPS (NHEADS / NKV)     // 4
#define KVDIM (NKV * HDIM)        // 512
#define ATTN_SCALE 0.125f         // 64^-0.5

// ---------------- scratch (static device globals; no allocation) ----------
__device__ float g_Q[(size_t)TOK * DMODEL];
__device__ float g_K[(size_t)TOK * KVDIM];
__device__ float g_V[(size_t)TOK * KVDIM];
__device__ float g_attn[(size_t)TOK * DMODEL];
__device__ __align__(16) __nv_bfloat16 g_Ahi[(size_t)TOK * DMODEL];
__device__ __align__(16) __nv_bfloat16 g_Alo[(size_t)TOK * DMODEL];
__device__ __align__(16) __nv_bfloat16 g_Bhi[(size_t)DMODEL * DMODEL];  // [N,K]
__device__ __align__(16) __nv_bfloat16 g_Blo[(size_t)DMODEL * DMODEL];
// bf16 hi/lo attention operands (rope+scale applied to Q/K)
__device__ __align__(16) __nv_bfloat16 g_Qh[(size_t)TOK * DMODEL];
__device__ __align__(16) __nv_bfloat16 g_Ql[(size_t)TOK * DMODEL];
__device__ __align__(16) __nv_bfloat16 g_Kh[(size_t)TOK * KVDIM];
__device__ __align__(16) __nv_bfloat16 g_Kl[(size_t)TOK * KVDIM];
__device__ __align__(16) __nv_bfloat16 g_Vh[(size_t)TOK * KVDIM];
__device__ __align__(16) __nv_bfloat16 g_Vl[(size_t)TOK * KVDIM];

// =================== PTX helpers (compute_103-safe, sm_80-era) =============
__device__ __forceinline__ uint32_t smem_u32(const void* p) {
    uint32_t a;
    asm("{ .reg .u64 t; cvta.to.shared.u64 t, %1; cvt.u32.u64 %0, t; }"
        : "=r"(a) : "l"(p));
    return a;
}

#define CP_ASYNC16(dst, src) \
    asm volatile("cp.async.cg.shared.global [%0], [%1], 16;" \
                 :: "r"(dst), "l"(src) : "memory")
#define CP_COMMIT() asm volatile("cp.async.commit_group;" ::: "memory")
#define CP_WAIT1()  asm volatile("cp.async.wait_group 1;" ::: "memory")
#define CP_WAIT0()  asm volatile("cp.async.wait_group 0;" ::: "memory")

#define LDMATRIX_X4(r0, r1, r2, r3, addr) \
    asm volatile("ldmatrix.sync.aligned.m8n8.x4.shared.b16 {%0,%1,%2,%3}, [%4];" \
                 : "=r"(r0), "=r"(r1), "=r"(r2), "=r"(r3) : "r"(addr))

#define LDMATRIX_X4T(r0, r1, r2, r3, addr) \
    asm volatile("ldmatrix.sync.aligned.m8n8.x4.trans.shared.b16 {%0,%1,%2,%3}, [%4];" \
                 : "=r"(r0), "=r"(r1), "=r"(r2), "=r"(r3) : "r"(addr))

#define MMA16816(d, a, b) \
    asm volatile("mma.sync.aligned.m16n8k16.row.col.f32.bf16.bf16.f32 " \
                 "{%0,%1,%2,%3}, {%4,%5,%6,%7}, {%8,%9}, {%0,%1,%2,%3};" \
                 : "+f"((d)[0]), "+f"((d)[1]), "+f"((d)[2]), "+f"((d)[3]) \
                 : "r"((a)[0]), "r"((a)[1]), "r"((a)[2]), "r"((a)[3]), \
                   "r"((b)[0]), "r"((b)[1]))

// =================== conversion kernels =====================================
__global__ void split_kernel(const float* __restrict__ A,
                             __nv_bfloat162* __restrict__ H,
                             __nv_bfloat162* __restrict__ L, int n4)
{
    int i = blockIdx.x * blockDim.x + threadIdx.x;
    if (i >= n4) return;
    float4 v = reinterpret_cast<const float4*>(A)[i];
    __nv_bfloat16 h0 = __float2bfloat16(v.x);
    __nv_bfloat16 h1 = __float2bfloat16(v.y);
    __nv_bfloat16 h2 = __float2bfloat16(v.z);
    __nv_bfloat16 h3 = __float2bfloat16(v.w);
    __nv_bfloat16 l0 = __float2bfloat16(v.x - __bfloat162float(h0));
    __nv_bfloat16 l1 = __float2bfloat16(v.y - __bfloat162float(h1));
    __nv_bfloat16 l2 = __float2bfloat16(v.z - __bfloat162float(h2));
    __nv_bfloat16 l3 = __float2bfloat16(v.w - __bfloat162float(h3));
    H[2 * i]     = __nv_bfloat162(h0, h1);
    H[2 * i + 1] = __nv_bfloat162(h2, h3);
    L[2 * i]     = __nv_bfloat162(l0, l1);
    L[2 * i + 1] = __nv_bfloat162(l2, l3);
}

// W [2048, N] row-major -> Th/Tl [N, 2048] transposed + bf16 hi/lo split.
__global__ void transpose_split(const float* __restrict__ W,
                                __nv_bfloat16* __restrict__ Th,
                                __nv_bfloat16* __restrict__ Tl, int N)
{
    __shared__ float tile[32][33];
    int n = blockIdx.x * 32 + threadIdx.x;
    int k = blockIdx.y * 32 + threadIdx.y;
#pragma unroll
    for (int j = 0; j < 32; j += 8)
        tile[threadIdx.y + j][threadIdx.x] = W[(size_t)(k + j) * N + n];
    __syncthreads();
    int k2 = blockIdx.y * 32 + threadIdx.x;
    int n2 = blockIdx.x * 32 + threadIdx.y;
#pragma unroll
    for (int j = 0; j < 32; j += 8) {
        float v = tile[threadIdx.x][threadIdx.y + j];
        __nv_bfloat16 h = __float2bfloat16(v);
        Th[(size_t)(n2 + j) * DMODEL + k2] = h;
        Tl[(size_t)(n2 + j) * DMODEL + k2] =
            __float2bfloat16(v - __bfloat162float(h));
    }
}

// RoPE + scale + bf16 hi/lo split: X fp32 [T, H*64] -> Xh/Xl bf16.
__global__ void rope_split(const float* __restrict__ X,
                           const float* __restrict__ cs,
                           const float* __restrict__ sn,
                           __nv_bfloat16* __restrict__ Xh,
                           __nv_bfloat16* __restrict__ Xl,
                           int H, float scale)
{
    int idx = blockIdx.x * blockDim.x + threadIdx.x;
    int total = TOK * H * 32;
    if (idx >= total) return;
    int i = idx & 31;
    int h = (idx >> 5) % H;
    int t = idx / (32 * H);
    float c = cs[t * 32 + i];
    float s = sn[t * 32 + i];
    size_t base = (size_t)t * (H * HDIM) + h * HDIM;
    float x1 = X[base + i], x2 = X[base + i + 32];
    float y1 = (x1 * c - x2 * s) * scale;
    float y2 = (x2 * c + x1 * s) * scale;
    __nv_bfloat16 h1 = __float2bfloat16(y1);
    __nv_bfloat16 h2 = __float2bfloat16(y2);
    Xh[base + i]      = h1;
    Xh[base + i + 32] = h2;
    Xl[base + i]      = __float2bfloat16(y1 - __bfloat162float(h1));
    Xl[base + i + 32] = __float2bfloat16(y2 - __bfloat162float(h2));
}

// =================== HMMA GEMM (verified R6) ================================
#define BM 128
#define BN 128
#define BK 32
#define TILE_B (128 * BK * 2)
#define STAGE_B (4 * TILE_B)
#define GEMM_SMEM (2 * STAGE_B)

__device__ __forceinline__ uint32_t sw_off(int row, int c16) {
    return (uint32_t)(row * 64 + ((c16 ^ (row & 3)) * 16));
}

__device__ __forceinline__ void stage_load(
    const __nv_bfloat16* __restrict__ aH, const __nv_bfloat16* __restrict__ aL,
    const __nv_bfloat16* __restrict__ bH, const __nv_bfloat16* __restrict__ bL,
    uint32_t sbase, int k0, int tid)
{
#pragma unroll
    for (int j = 0; j < 2; j++) {
        int i = tid + j * 256;
        int row = i >> 2;
        int c16 = i & 3;
        uint32_t doff = sw_off(row, c16);
        size_t goff = (size_t)row * DMODEL + k0 + c16 * 8;
        CP_ASYNC16(sbase + 0 * TILE_B + doff, aH + goff);
        CP_ASYNC16(sbase + 1 * TILE_B + doff, aL + goff);
        CP_ASYNC16(sbase + 2 * TILE_B + doff, bH + goff);
        CP_ASYNC16(sbase + 3 * TILE_B + doff, bL + goff);
    }
}

__global__ void __launch_bounds__(256, 1) gemm_mma(
    const __nv_bfloat16* __restrict__ Ahi, const __nv_bfloat16* __restrict__ Alo,
    const __nv_bfloat16* __restrict__ Bhi, const __nv_bfloat16* __restrict__ Blo,
    float* __restrict__ C, int N)
{
    extern __shared__ char smem[];
    uint32_t sb = smem_u32(smem);
    const int tid = threadIdx.x;
    const int lane = tid & 31;
    const int wid = tid >> 5;
    const int wm = wid >> 2;
    const int wn = wid & 3;
    const int brow = blockIdx.y * BM;
    const int bcol = blockIdx.x * BN;

    const __nv_bfloat16* aH = Ahi + (size_t)brow * DMODEL;
    const __nv_bfloat16* aL = Alo + (size_t)brow * DMODEL;
    const __nv_bfloat16* bH = Bhi + (size_t)bcol * DMODEL;
    const __nv_bfloat16* bL = Blo + (size_t)bcol * DMODEL;

    float acc[4][4][4];
#pragma unroll
    for (int i = 0; i < 4; i++)
#pragma unroll
        for (int j = 0; j < 4; j++)
#pragma unroll
            for (int q = 0; q < 4; q++) acc[i][j][q] = 0.f;

    const int NC = DMODEL / BK;
    stage_load(aH, aL, bH, bL, sb, 0, tid);
    CP_COMMIT();

    for (int c = 0; c < NC; c++) {
        uint32_t st = sb + (uint32_t)(c & 1) * STAGE_B;
        if (c + 1 < NC) {
            stage_load(aH, aL, bH, bL, sb + (uint32_t)((c + 1) & 1) * STAGE_B,
                       (c + 1) * BK, tid);
            CP_COMMIT();
            CP_WAIT1();
        } else {
            CP_WAIT0();
        }
        __syncthreads();

#pragma unroll
        for (int ks = 0; ks < 2; ks++) {
            uint32_t fAh[4][4], fAl[4][4];
#pragma unroll
            for (int mt = 0; mt < 4; mt++) {
                int row = wm * 64 + mt * 16 + (lane & 15);
                int c16 = ks * 2 + (lane >> 4);
                uint32_t off = sw_off(row, c16);
                LDMATRIX_X4(fAh[mt][0], fAh[mt][1], fAh[mt][2], fAh[mt][3],
                            st + 0 * TILE_B + off);
                LDMATRIX_X4(fAl[mt][0], fAl[mt][1], fAl[mt][2], fAl[mt][3],
                            st + 1 * TILE_B + off);
            }
            uint32_t fBh[4][2], fBl[4][2];
#pragma unroll
            for (int pr = 0; pr < 2; pr++) {
                int nrel = wn * 32 + pr * 16 + ((lane >> 4) * 8 + (lane & 7));
                int c16 = ks * 2 + ((lane >> 3) & 1);
                uint32_t off = sw_off(nrel, c16);
                LDMATRIX_X4(fBh[2 * pr][0], fBh[2 * pr][1],
                            fBh[2 * pr + 1][0], fBh[2 * pr + 1][1],
                            st + 2 * TILE_B + off);
                LDMATRIX_X4(fBl[2 * pr][0], fBl[2 * pr][1],
                            fBl[2 * pr + 1][0], fBl[2 * pr + 1][1],
                            st + 3 * TILE_B + off);
            }
#pragma unroll
            for (int mt = 0; mt < 4; mt++)
#pragma unroll
                for (int nt = 0; nt < 4; nt++) {
                    MMA16816(acc[mt][nt], fAh[mt], fBh[nt]);
                    MMA16816(acc[mt][nt], fAh[mt], fBl[nt]);
                    MMA16816(acc[mt][nt], fAl[mt], fBh[nt]);
                }
        }
        __syncthreads();
    }

#pragma unroll
    for (int mt = 0; mt < 4; mt++) {
#pragma unroll
        for (int nt = 0; nt < 4; nt++) {
            int m = brow + wm * 64 + mt * 16 + (lane >> 2);
            int n = bcol + wn * 32 + nt * 8 + (lane & 3) * 2;
            float2 v0 = make_float2(acc[mt][nt][0], acc[mt][nt][1]);
            float2 v1 = make_float2(acc[mt][nt][2], acc[mt][nt][3]);
            *reinterpret_cast<float2*>(C + (size_t)m * N + n) = v0;
            *reinterpret_cast<float2*>(C + (size_t)(m + 8) * N + n) = v1;
        }
    }
}

// =================== tensor-core flash attention ============================
// CTA: 128 q-rows of one (b, h). 4 warps x 32 q-rows (2 m-tiles of 16).
// K/V blocks of 64 keys, double-buffered cp.async. Hi/lo bf16 HMMA for both
// S = Q K^T (3 terms) and O += P V (3 terms). fp32 online softmax.

// 128-byte rows, 8 chunk swizzle
__device__ __forceinline__ uint32_t swz8(int row, int c16) {
    return (uint32_t)(row * 128 + ((c16 ^ (row & 7)) * 16));
}

#define FQ_SMEM 32768                 // Qh 16K + Ql 16K
#define KV_BUF  32768                 // Kh/Kl/Vh/Vl 8K each
#define FLASH_SMEM (FQ_SMEM + 2 * KV_BUF)   // 98304

__device__ __forceinline__ void stage_kv(
    const __nv_bfloat16* __restrict__ Kh, const __nv_bfloat16* __restrict__ Kl,
    const __nv_bfloat16* __restrict__ Vh, const __nv_bfloat16* __restrict__ Vl,
    uint32_t sbase, size_t gbase, int tid)
{
#pragma unroll
    for (int t = 0; t < 4; t++) {
        int i = tid + t * 128;
        int row = i >> 3;
        int c16 = i & 7;
        uint32_t doff = swz8(row, c16);
        size_t goff = gbase + (size_t)row * KVDIM + c16 * 8;
        CP_ASYNC16(sbase + 0     + doff, Kh + goff);
        CP_ASYNC16(sbase + 8192  + doff, Kl + goff);
        CP_ASYNC16(sbase + 16384 + doff, Vh + goff);
        CP_ASYNC16(sbase + 24576 + doff, Vl + goff);
    }
}

__global__ void __launch_bounds__(128) flash_mma(
    const __nv_bfloat16* __restrict__ Qh, const __nv_bfloat16* __restrict__ Ql,
    const __nv_bfloat16* __restrict__ Kh, const __nv_bfloat16* __restrict__ Kl,
    const __nv_bfloat16* __restrict__ Vh, const __nv_bfloat16* __restrict__ Vl,
    float* __restrict__ O)
{
    extern __shared__ char smem[];
    uint32_t sb = smem_u32(smem);
    const int qt = blockIdx.x;      // 0..7 (128-row q tiles)
    const int h  = blockIdx.y;      // 0..31
    const int b  = blockIdx.z;      // 0..3
    const int kvh = h / GROUPS;
    const int tid = threadIdx.x;
    const int lane = tid & 31;
    const int w = tid >> 5;         // warp 0..3
    const int qbase = qt * 128;

    // ---- stage Q tile (hi/lo) ----
#pragma unroll
    for (int t = 0; t < 8; t++) {
        int i = tid + t * 128;
        int row = i >> 3;
        int c16 = i & 7;
        uint32_t doff = swz8(row, c16);
        size_t goff = (size_t)(b * SEQ + qbase + row) * DMODEL + h * HDIM + c16 * 8;
        CP_ASYNC16(sb + doff, Qh + goff);
        CP_ASYNC16(sb + 16384 + doff, Ql + goff);
    }
    // ---- stage KV block 0 ----
    size_t kvg0 = (size_t)(b * SEQ) * KVDIM + kvh * HDIM;
    stage_kv(Kh, Kl, Vh, Vl, sb + FQ_SMEM, kvg0, tid);
    CP_COMMIT();

    // per-warp state
    float acc[2][8][4];
#pragma unroll
    for (int mt = 0; mt < 2; mt++)
#pragma unroll
        for (int nt = 0; nt < 8; nt++)
#pragma unroll
            for (int e = 0; e < 4; e++) acc[mt][nt][e] = 0.f;
    float mrow[2][2] = {{-CUDART_INF_F, -CUDART_INF_F},
                        {-CUDART_INF_F, -CUDART_INF_F}};
    float lrow[2][2] = {{0.f, 0.f}, {0.f, 0.f}};

    const int nb = 2 * qt + 2;      // 64-key blocks
    for (int c = 0; c < nb; c++) {
        if (c + 1 < nb) {
            stage_kv(Kh, Kl, Vh, Vl, sb + FQ_SMEM + ((c + 1) & 1) * KV_BUF,
                     kvg0 + (size_t)(c + 1) * 64 * KVDIM, tid);
            CP_COMMIT();
            CP_WAIT1();
        } else {
            CP_WAIT0();
        }
        __syncthreads();

        uint32_t sk = sb + FQ_SMEM + (c & 1) * KV_BUF;

        // ---- S = Q K^T (hi/lo corrected) ----
        float S[2][8][4];
#pragma unroll
        for (int mt = 0; mt < 2; mt++)
#pragma unroll
            for (int nt = 0; nt < 8; nt++)
#pragma unroll
                for (int e = 0; e < 4; e++) S[mt][nt][e] = 0.f;

#pragma unroll
        for (int ks = 0; ks < 4; ks++) {
            uint32_t qh[2][4], ql[2][4];
#pragma unroll
            for (int mt = 0; mt < 2; mt++) {
                int row = w * 32 + mt * 16 + (lane & 15);
                int c16 = ks * 2 + (lane >> 4);
                uint32_t off = swz8(row, c16);
                LDMATRIX_X4(qh[mt][0], qh[mt][1], qh[mt][2], qh[mt][3], sb + off);
                LDMATRIX_X4(ql[mt][0], ql[mt][1], ql[mt][2], ql[mt][3],
                            sb + 16384 + off);
            }
#pragma unroll
            for (int np = 0; np < 4; np++) {
                int row = np * 16 + ((lane >> 4) * 8) + (lane & 7);
                int c16 = ks * 2 + ((lane >> 3) & 1);
                uint32_t off = swz8(row, c16);
                uint32_t kh[4], kl[4];
                LDMATRIX_X4(kh[0], kh[1], kh[2], kh[3], sk + off);
                LDMATRIX_X4(kl[0], kl[1], kl[2], kl[3], sk + 8192 + off);
#pragma unroll
                for (int mt = 0; mt < 2; mt++) {
                    MMA16816(S[mt][2 * np],     qh[mt], (kh + 0));
                    MMA16816(S[mt][2 * np + 1], qh[mt], (kh + 2));
                    MMA16816(S[mt][2 * np],     qh[mt], (kl + 0));
                    MMA16816(S[mt][2 * np + 1], qh[mt], (kl + 2));
                    MMA16816(S[mt][2 * np],     ql[mt], (kh + 0));
                    MMA16816(S[mt][2 * np + 1], ql[mt], (kh + 2));
                }
            }
        }

        // ---- causal mask (only blocks touching the diagonal) ----
        if (c >= 2 * qt) {
            int kb = c * 64;
#pragma unroll
            for (int mt = 0; mt < 2; mt++) {
                int r0 = qbase + w * 32 + mt * 16 + (lane >> 2);
#pragma unroll
                for (int nt = 0; nt < 8; nt++) {
                    int key = kb + nt * 8 + (lane & 3) * 2;
                    if (key > r0)     S[mt][nt][0] = -CUDART_INF_F;
                    if (key + 1 > r0) S[mt][nt][1] = -CUDART_INF_F;
                    if (key > r0 + 8)     S[mt][nt][2] = -CUDART_INF_F;
                    if (key + 1 > r0 + 8) S[mt][nt][3] = -CUDART_INF_F;
                }
            }
        }

        // ---- online softmax (fp32) ----
        uint32_t aPh[2][4][4], aPl[2][4][4];
#pragma unroll
        for (int mt = 0; mt < 2; mt++) {
#pragma unroll
            for (int e2 = 0; e2 < 2; e2++) {
                float mx = -CUDART_INF_F;
#pragma unroll
                for (int nt = 0; nt < 8; nt++)
                    mx = fmaxf(mx, fmaxf(S[mt][nt][2 * e2], S[mt][nt][2 * e2 + 1]));
                mx = fmaxf(mx, __shfl_xor_sync(0xffffffffu, mx, 1));
                mx = fmaxf(mx, __shfl_xor_sync(0xffffffffu, mx, 2));
                float mn = fmaxf(mrow[mt][e2], mx);
                float alpha = __expf(mrow[mt][e2] - mn);
                mrow[mt][e2] = mn;
                float sum = 0.f;
#pragma unroll
                for (int nt = 0; nt < 8; nt++) {
                    float p0 = __expf(S[mt][nt][2 * e2] - mn);
                    float p1 = __expf(S[mt][nt][2 * e2 + 1] - mn);
                    S[mt][nt][2 * e2] = p0;
                    S[mt][nt][2 * e2 + 1] = p1;
                    sum += p0 + p1;
                }
                sum += __shfl_xor_sync(0xffffffffu, sum, 1);
                sum += __shfl_xor_sync(0xffffffffu, sum, 2);
                lrow[mt][e2] = lrow[mt][e2] * alpha + sum;
#pragma unroll
                for (int nt = 0; nt < 8; nt++) {
                    acc[mt][nt][2 * e2] *= alpha;
                    acc[mt][nt][2 * e2 + 1] *= alpha;
                }
            }
            // P (fp32) -> bf16 hi/lo A-fragments
#pragma unroll
            for (int kc = 0; kc < 4; kc++) {
#pragma unroll
                for (int r = 0; r < 4; r++) {
                    int nt = 2 * kc + (r >> 1);
                    int e0 = (r & 1) * 2;
                    float p0 = S[mt][nt][e0], p1 = S[mt][nt][e0 + 1];
                    __nv_bfloat162 hh = __floats2bfloat162_rn(p0, p1);
                    float r0 = p0 - __bfloat162float(hh.x);
                    float r1 = p1 - __bfloat162float(hh.y);
                    __nv_bfloat162 ll = __floats2bfloat162_rn(r0, r1);
                    aPh[mt][kc][r] = *reinterpret_cast<uint32_t*>(&hh);
                    aPl[mt][kc][r] = *reinterpret_cast<uint32_t*>(&ll);
                }
            }
        }

        // ---- O += P V (hi/lo corrected) ----
#pragma unroll
        for (int kc = 0; kc < 4; kc++) {
#pragma unroll
            for (int dp = 0; dp < 4; dp++) {
                int row = kc * 16 + ((lane >> 3) & 1) * 8 + (lane & 7);
                int c16 = dp * 2 + (lane >> 4);
                uint32_t off = swz8(row, c16);
                uint32_t vh[4], vl[4];
                LDMATRIX_X4T(vh[0], vh[1], vh[2], vh[3], sk + 16384 + off);
                LDMATRIX_X4T(vl[0], vl[1], vl[2], vl[3], sk + 24576 + off);
#pragma unroll
                for (int mt = 0; mt < 2; mt++) {
                    MMA16816(acc[mt][2 * dp],     aPh[mt][kc], (vh + 0));
                    MMA16816(acc[mt][2 * dp + 1], aPh[mt][kc], (vh + 2));
                    MMA16816(acc[mt][2 * dp],     aPh[mt][kc], (vl + 0));
                    MMA16816(acc[mt][2 * dp + 1], aPh[mt][kc], (vl + 2));
                    MMA16816(acc[mt][2 * dp],     aPl[mt][kc], (vh + 0));
                    MMA16816(acc[mt][2 * dp + 1], aPl[mt][kc], (vh + 2));
                }
            }
        }
        __syncthreads();
    }

    // ---- epilogue: O / l -> g_attn ----
#pragma unroll
    for (int mt = 0; mt < 2; mt++) {
        float inv0 = 1.0f / lrow[mt][0];
        float inv1 = 1.0f / lrow[mt][1];
        int r0 = qbase + w * 32 + mt * 16 + (lane >> 2);
        size_t t0 = (size_t)(b * SEQ + r0) * DMODEL + h * HDIM;
        size_t t1 = t0 + 8 * DMODEL;
#pragma unroll
        for (int nt = 0; nt < 8; nt++) {
            int d = nt * 8 + (lane & 3) * 2;
            float2 v0 = make_float2(acc[mt][nt][0] * inv0, acc[mt][nt][1] * inv0);
            float2 v1 = make_float2(acc[mt][nt][2] * inv1, acc[mt][nt][3] * inv1);
            *reinterpret_cast<float2*>(O + t0 + d) = v0;
            *reinterpret_cast<float2*>(O + t1 + d) = v1;
        }
    }
}

// ---------------- launch ----------------------------------------------------
extern "C" void kernel_launch(void* const* d_in, const int* in_sizes, int n_in,
                              void* d_out, int out_size)
{
    const float* hidden = (const float*)d_in[0];
    const float* cs     = (const float*)d_in[1];
    const float* sn     = (const float*)d_in[2];
    const float* Wq     = (const float*)d_in[3];
    const float* Wk     = (const float*)d_in[4];
    const float* Wv     = (const float*)d_in[5];
    const float* Wo     = (const float*)d_in[6];
    float* out          = (float*)d_out;

    float* Q  = nullptr; cudaGetSymbolAddress((void**)&Q,  g_Q);
    float* Kp = nullptr; cudaGetSymbolAddress((void**)&Kp, g_K);
    float* Vp = nullptr; cudaGetSymbolAddress((void**)&Vp, g_V);
    float* At = nullptr; cudaGetSymbolAddress((void**)&At, g_attn);
    __nv_bfloat16* Ah = nullptr; cudaGetSymbolAddress((void**)&Ah, g_Ahi);
    __nv_bfloat16* Al = nullptr; cudaGetSymbolAddress((void**)&Al, g_Alo);
    __nv_bfloat16* Bh = nullptr; cudaGetSymbolAddress((void**)&Bh, g_Bhi);
    __nv_bfloat16* Bl = nullptr; cudaGetSymbolAddress((void**)&Bl, g_Blo);
    __nv_bfloat16* Qh = nullptr; cudaGetSymbolAddress((void**)&Qh, g_Qh);
    __nv_bfloat16* Ql = nullptr; cudaGetSymbolAddress((void**)&Ql, g_Ql);
    __nv_bfloat16* Kh = nullptr; cudaGetSymbolAddress((void**)&Kh, g_Kh);
    __nv_bfloat16* Kl = nullptr; cudaGetSymbolAddress((void**)&Kl, g_Kl);
    __nv_bfloat16* Vh = nullptr; cudaGetSymbolAddress((void**)&Vh, g_Vh);
    __nv_bfloat16* Vl = nullptr; cudaGetSymbolAddress((void**)&Vl, g_Vl);

    static bool attr_set = false;
    if (!attr_set) {
        cudaFuncSetAttribute(gemm_mma, cudaFuncAttributeMaxDynamicSharedMemorySize,
                             GEMM_SMEM);
        cudaFuncSetAttribute(flash_mma, cudaFuncAttributeMaxDynamicSharedMemorySize,
                             FLASH_SMEM);
        attr_set = true;
    }

    const int n4 = TOK * DMODEL / 4;

    // split hidden -> bf16 hi/lo
    split_kernel<<<n4 / 256, 256>>>(hidden, (__nv_bfloat162*)Ah,
                                    (__nv_bfloat162*)Al, n4);

    // Q = hidden @ Wq
    transpose_split<<<dim3(DMODEL / 32, DMODEL / 32), dim3(32, 8)>>>(Wq, Bh, Bl, DMODEL);
    gemm_mma<<<dim3(DMODEL / BN, TOK / BM), 256, GEMM_SMEM>>>(Ah, Al, Bh, Bl, Q, DMODEL);

    // K = hidden @ Wk
    transpose_split<<<dim3(KVDIM / 32, DMODEL / 32), dim3(32, 8)>>>(Wk, Bh, Bl, KVDIM);
    gemm_mma<<<dim3(KVDIM / BN, TOK / BM), 256, GEMM_SMEM>>>(Ah, Al, Bh, Bl, Kp, KVDIM);

    // V = hidden @ Wv
    transpose_split<<<dim3(KVDIM / 32, DMODEL / 32), dim3(32, 8)>>>(Wv, Bh, Bl, KVDIM);
    gemm_mma<<<dim3(KVDIM / BN, TOK / BM), 256, GEMM_SMEM>>>(Ah, Al, Bh, Bl, Vp, KVDIM);

    // RoPE + scale + split to bf16 hi/lo
    {
        int totq = TOK * NHEADS * 32;
        rope_split<<<(totq + 255) / 256, 256>>>(Q, cs, sn, Qh, Ql, NHEADS, ATTN_SCALE);
        int totk = TOK * NKV * 32;
        rope_split<<<(totk + 255) / 256, 256>>>(Kp, cs, sn, Kh, Kl, NKV, 1.0f);
        int nv4 = TOK * KVDIM / 4;
        split_kernel<<<nv4 / 256, 256>>>(Vp, (__nv_bfloat162*)Vh,
                                         (__nv_bfloat162*)Vl, nv4);
    }

    // tensor-core flash attention
    {
        dim3 grid(SEQ / 128, NHEADS, BSZ);
        flash_mma<<<grid, 128, FLASH_SMEM>>>(Qh, Ql, Kh, Kl, Vh, Vl, At);
    }

    // out = attn @ Wo
    split_kernel<<<n4 / 256, 256>>>(At, (__nv_bfloat162*)Ah, (__nv_bfloat162*)Al, n4);
    transpose_split<<<dim3(DMODEL / 32, DMODEL / 32), dim3(32, 8)>>>(Wo, Bh, Bl, DMODEL);
    gemm_mma<<<dim3(DMODEL / BN, TOK / BM), 256, GEMM_SMEM>>>(Ah, Al, Bh, Bl, out, DMODEL);
}

// round 8
// speedup vs baseline: 4.1036x; 1.3048x over previous
#include <cuda_runtime.h>
#include <cuda_bf16.h>
#include <cstdint>
#include <math_constants.h>

// Problem constants
#define BSZ 4
#define SEQ 1024
#define TOK (BSZ * SEQ)          // 4096
#define DMODEL 2048
#define NHEADS 32
#define NKV 8
#define HDIM 64
#define GROUPS (NHEADS / NKV)     // 4
#define KVDIM (NKV * HDIM)        // 512
#define QKVN (DMODEL + 2 * KVDIM) // 3072
#define ATTN_SCALE 0.125f

// ---------------- scratch (static device globals; no allocation) ----------
__device__ float g_QKV[(size_t)TOK * QKVN];                       // fused QKV out
__device__ __align__(16) __nv_bfloat16 g_Ahi[(size_t)TOK * DMODEL];  // A hi (hidden, then attn)
__device__ __align__(16) __nv_bfloat16 g_Alo[(size_t)TOK * DMODEL];
__device__ __align__(16) __nv_bfloat16 g_Bhi[(size_t)QKVN * DMODEL]; // [N,K] weights
__device__ __align__(16) __nv_bfloat16 g_Blo[(size_t)QKVN * DMODEL];
__device__ __align__(16) __nv_bfloat16 g_Qh[(size_t)TOK * DMODEL];
__device__ __align__(16) __nv_bfloat16 g_Ql[(size_t)TOK * DMODEL];
__device__ __align__(16) __nv_bfloat16 g_Kh[(size_t)TOK * KVDIM];
__device__ __align__(16) __nv_bfloat16 g_Kl[(size_t)TOK * KVDIM];
__device__ __align__(16) __nv_bfloat16 g_Vh[(size_t)TOK * KVDIM];
__device__ __align__(16) __nv_bfloat16 g_Vl[(size_t)TOK * KVDIM];

// =================== PTX helpers (compute_103-safe) =========================
__device__ __forceinline__ uint32_t smem_u32(const void* p) {
    uint32_t a;
    asm("{ .reg .u64 t; cvta.to.shared.u64 t, %1; cvt.u32.u64 %0, t; }"
        : "=r"(a) : "l"(p));
    return a;
}

#define CP_ASYNC16(dst, src) \
    asm volatile("cp.async.cg.shared.global [%0], [%1], 16;" \
                 :: "r"(dst), "l"(src) : "memory")
#define CP_COMMIT() asm volatile("cp.async.commit_group;" ::: "memory")
#define CP_WAIT2()  asm volatile("cp.async.wait_group 2;" ::: "memory")
#define CP_WAIT1()  asm volatile("cp.async.wait_group 1;" ::: "memory")
#define CP_WAIT0()  asm volatile("cp.async.wait_group 0;" ::: "memory")

#define LDMATRIX_X4(r0, r1, r2, r3, addr) \
    asm volatile("ldmatrix.sync.aligned.m8n8.x4.shared.b16 {%0,%1,%2,%3}, [%4];" \
                 : "=r"(r0), "=r"(r1), "=r"(r2), "=r"(r3) : "r"(addr))

#define LDMATRIX_X4T(r0, r1, r2, r3, addr) \
    asm volatile("ldmatrix.sync.aligned.m8n8.x4.trans.shared.b16 {%0,%1,%2,%3}, [%4];" \
                 : "=r"(r0), "=r"(r1), "=r"(r2), "=r"(r3) : "r"(addr))

#define MMA16816(d, a, b) \
    asm volatile("mma.sync.aligned.m16n8k16.row.col.f32.bf16.bf16.f32 " \
                 "{%0,%1,%2,%3}, {%4,%5,%6,%7}, {%8,%9}, {%0,%1,%2,%3};" \
                 : "+f"((d)[0]), "+f"((d)[1]), "+f"((d)[2]), "+f"((d)[3]) \
                 : "r"((a)[0]), "r"((a)[1]), "r"((a)[2]), "r"((a)[3]), \
                   "r"((b)[0]), "r"((b)[1]))

// 128-byte rows, 8-chunk swizzle (used by GEMM and flash)
__device__ __forceinline__ uint32_t swz8(int row, int c16) {
    return (uint32_t)(row * 128 + ((c16 ^ (row & 7)) * 16));
}

// =================== conversion kernels =====================================
__global__ void split_kernel(const float* __restrict__ A,
                             __nv_bfloat162* __restrict__ H,
                             __nv_bfloat162* __restrict__ L, int n4)
{
    int i = blockIdx.x * blockDim.x + threadIdx.x;
    if (i >= n4) return;
    float4 v = reinterpret_cast<const float4*>(A)[i];
    __nv_bfloat16 h0 = __float2bfloat16(v.x);
    __nv_bfloat16 h1 = __float2bfloat16(v.y);
    __nv_bfloat16 h2 = __float2bfloat16(v.z);
    __nv_bfloat16 h3 = __float2bfloat16(v.w);
    __nv_bfloat16 l0 = __float2bfloat16(v.x - __bfloat162float(h0));
    __nv_bfloat16 l1 = __float2bfloat16(v.y - __bfloat162float(h1));
    __nv_bfloat16 l2 = __float2bfloat16(v.z - __bfloat162float(h2));
    __nv_bfloat16 l3 = __float2bfloat16(v.w - __bfloat162float(h3));
    H[2 * i]     = __nv_bfloat162(h0, h1);
    H[2 * i + 1] = __nv_bfloat162(h2, h3);
    L[2 * i]     = __nv_bfloat162(l0, l1);
    L[2 * i + 1] = __nv_bfloat162(l2, l3);
}

// strided split: X [T, xstride] slice starting at xoff, width cols -> packed
__global__ void split_strided(const float* __restrict__ X, int xstride, int xoff,
                              __nv_bfloat162* __restrict__ H,
                              __nv_bfloat162* __restrict__ L, int cols)
{
    int idx = blockIdx.x * blockDim.x + threadIdx.x;
    int c4 = cols / 4;
    int row = idx / c4;
    int c = idx % c4;
    if (row >= TOK) return;
    float4 v = *reinterpret_cast<const float4*>(X + (size_t)row * xstride + xoff + c * 4);
    __nv_bfloat16 h0 = __float2bfloat16(v.x);
    __nv_bfloat16 h1 = __float2bfloat16(v.y);
    __nv_bfloat16 h2 = __float2bfloat16(v.z);
    __nv_bfloat16 h3 = __float2bfloat16(v.w);
    size_t o = ((size_t)row * cols + c * 4) / 2;
    H[o]     = __nv_bfloat162(h0, h1);
    H[o + 1] = __nv_bfloat162(h2, h3);
    L[o]     = __nv_bfloat162(__float2bfloat16(v.x - __bfloat162float(h0)),
                              __float2bfloat16(v.y - __bfloat162float(h1)));
    L[o + 1] = __nv_bfloat162(__float2bfloat16(v.z - __bfloat162float(h2)),
                              __float2bfloat16(v.w - __bfloat162float(h3)));
}

// W [2048, N] row-major -> (Th/Tl)[rowoff + n][k] transposed + hi/lo split.
__global__ void transpose_split(const float* __restrict__ W,
                                __nv_bfloat16* __restrict__ Th,
                                __nv_bfloat16* __restrict__ Tl, int N, int rowoff)
{
    __shared__ float tile[32][33];
    int n = blockIdx.x * 32 + threadIdx.x;
    int k = blockIdx.y * 32 + threadIdx.y;
#pragma unroll
    for (int j = 0; j < 32; j += 8)
        tile[threadIdx.y + j][threadIdx.x] = W[(size_t)(k + j) * N + n];
    __syncthreads();
    int k2 = blockIdx.y * 32 + threadIdx.x;
    int n2 = blockIdx.x * 32 + threadIdx.y + rowoff;
#pragma unroll
    for (int j = 0; j < 32; j += 8) {
        float v = tile[threadIdx.x][threadIdx.y + j];
        __nv_bfloat16 h = __float2bfloat16(v);
        Th[(size_t)(n2 + j) * DMODEL + k2] = h;
        Tl[(size_t)(n2 + j) * DMODEL + k2] =
            __float2bfloat16(v - __bfloat162float(h));
    }
}

// RoPE + scale + hi/lo split: X [T, xstride] at col xoff, heads H -> packed.
__global__ void rope_split(const float* __restrict__ X, int xstride, int xoff,
                           const float* __restrict__ cs,
                           const float* __restrict__ sn,
                           __nv_bfloat16* __restrict__ Xh,
                           __nv_bfloat16* __restrict__ Xl,
                           int H, float scale)
{
    int idx = blockIdx.x * blockDim.x + threadIdx.x;
    int total = TOK * H * 32;
    if (idx >= total) return;
    int i = idx & 31;
    int h = (idx >> 5) % H;
    int t = idx / (32 * H);
    float c = cs[t * 32 + i];
    float s = sn[t * 32 + i];
    const float* in = X + (size_t)t * xstride + xoff + h * HDIM;
    size_t ob = (size_t)t * (H * HDIM) + h * HDIM;
    float x1 = in[i], x2 = in[i + 32];
    float y1 = (x1 * c - x2 * s) * scale;
    float y2 = (x2 * c + x1 * s) * scale;
    __nv_bfloat16 h1 = __float2bfloat16(y1);
    __nv_bfloat16 h2 = __float2bfloat16(y2);
    Xh[ob + i]      = h1;
    Xh[ob + i + 32] = h2;
    Xl[ob + i]      = __float2bfloat16(y1 - __bfloat162float(h1));
    Xl[ob + i + 32] = __float2bfloat16(y2 - __bfloat162float(h2));
}

// =================== HMMA GEMM: BK=64, 3-stage pipeline =====================
#define BM 128
#define BN 128
#define BK 64
#define TILE_B (128 * BK * 2)          // 16384
#define STAGE_B (4 * TILE_B)           // 65536
#define GEMM_SMEM (3 * STAGE_B)        // 196608

__device__ __forceinline__ void stage_load(
    const __nv_bfloat16* __restrict__ aH, const __nv_bfloat16* __restrict__ aL,
    const __nv_bfloat16* __restrict__ bH, const __nv_bfloat16* __restrict__ bL,
    uint32_t sbase, int k0, int tid)
{
#pragma unroll
    for (int j = 0; j < 4; j++) {
        int i = tid + j * 256;
        int row = i >> 3;
        int c16 = i & 7;
        uint32_t doff = swz8(row, c16);
        size_t goff = (size_t)row * DMODEL + k0 + c16 * 8;
        CP_ASYNC16(sbase + 0 * TILE_B + doff, aH + goff);
        CP_ASYNC16(sbase + 1 * TILE_B + doff, aL + goff);
        CP_ASYNC16(sbase + 2 * TILE_B + doff, bH + goff);
        CP_ASYNC16(sbase + 3 * TILE_B + doff, bL + goff);
    }
}

__global__ void __launch_bounds__(256, 1) gemm_mma(
    const __nv_bfloat16* __restrict__ Ahi, const __nv_bfloat16* __restrict__ Alo,
    const __nv_bfloat16* __restrict__ Bhi, const __nv_bfloat16* __restrict__ Blo,
    float* __restrict__ C, int N)
{
    extern __shared__ char smem[];
    uint32_t sb = smem_u32(smem);
    const int tid = threadIdx.x;
    const int lane = tid & 31;
    const int wid = tid >> 5;
    const int wm = wid >> 2;
    const int wn = wid & 3;
    const int brow = blockIdx.y * BM;
    const int bcol = blockIdx.x * BN;

    const __nv_bfloat16* aH = Ahi + (size_t)brow * DMODEL;
    const __nv_bfloat16* aL = Alo + (size_t)brow * DMODEL;
    const __nv_bfloat16* bH = Bhi + (size_t)bcol * DMODEL;
    const __nv_bfloat16* bL = Blo + (size_t)bcol * DMODEL;

    float acc[4][4][4];
#pragma unroll
    for (int i = 0; i < 4; i++)
#pragma unroll
        for (int j = 0; j < 4; j++)
#pragma unroll
            for (int q = 0; q < 4; q++) acc[i][j][q] = 0.f;

    const int NC = DMODEL / BK;   // 32
#pragma unroll
    for (int s = 0; s < 3; s++) {
        stage_load(aH, aL, bH, bL, sb + s * STAGE_B, s * BK, tid);
        CP_COMMIT();
    }

    for (int c = 0; c < NC; c++) {
        if (c + 2 < NC)      CP_WAIT2();
        else if (c + 1 < NC) CP_WAIT1();
        else                 CP_WAIT0();
        __syncthreads();

        uint32_t st = sb + (uint32_t)(c % 3) * STAGE_B;

#pragma unroll
        for (int ks = 0; ks < 4; ks++) {
            uint32_t fAh[4][4], fAl[4][4];
#pragma unroll
            for (int mt = 0; mt < 4; mt++) {
                int row = wm * 64 + mt * 16 + (lane & 15);
                int c16 = ks * 2 + (lane >> 4);
                uint32_t off = swz8(row, c16);
                LDMATRIX_X4(fAh[mt][0], fAh[mt][1], fAh[mt][2], fAh[mt][3],
                            st + 0 * TILE_B + off);
                LDMATRIX_X4(fAl[mt][0], fAl[mt][1], fAl[mt][2], fAl[mt][3],
                            st + 1 * TILE_B + off);
            }
            uint32_t fBh[4][2], fBl[4][2];
#pragma unroll
            for (int pr = 0; pr < 2; pr++) {
                int nrel = wn * 32 + pr * 16 + ((lane >> 4) * 8 + (lane & 7));
                int c16 = ks * 2 + ((lane >> 3) & 1);
                uint32_t off = swz8(nrel, c16);
                LDMATRIX_X4(fBh[2 * pr][0], fBh[2 * pr][1],
                            fBh[2 * pr + 1][0], fBh[2 * pr + 1][1],
                            st + 2 * TILE_B + off);
                LDMATRIX_X4(fBl[2 * pr][0], fBl[2 * pr][1],
                            fBl[2 * pr + 1][0], fBl[2 * pr + 1][1],
                            st + 3 * TILE_B + off);
            }
#pragma unroll
            for (int mt = 0; mt < 4; mt++)
#pragma unroll
                for (int nt = 0; nt < 4; nt++) {
                    MMA16816(acc[mt][nt], fAh[mt], fBh[nt]);
                    MMA16816(acc[mt][nt], fAh[mt], fBl[nt]);
                    MMA16816(acc[mt][nt], fAl[mt], fBh[nt]);
                }
        }
        __syncthreads();
        if (c + 3 < NC) {
            stage_load(aH, aL, bH, bL, st, (c + 3) * BK, tid);
            CP_COMMIT();
        }
    }

#pragma unroll
    for (int mt = 0; mt < 4; mt++) {
#pragma unroll
        for (int nt = 0; nt < 4; nt++) {
            int m = brow + wm * 64 + mt * 16 + (lane >> 2);
            int n = bcol + wn * 32 + nt * 8 + (lane & 3) * 2;
            float2 v0 = make_float2(acc[mt][nt][0], acc[mt][nt][1]);
            float2 v1 = make_float2(acc[mt][nt][2], acc[mt][nt][3]);
            *reinterpret_cast<float2*>(C + (size_t)m * N + n) = v0;
            *reinterpret_cast<float2*>(C + (size_t)(m + 8) * N + n) = v1;
        }
    }
}

// =================== tensor-core flash attention ============================
#define FQ_SMEM 32768
#define KV_BUF  32768
#define FLASH_SMEM (FQ_SMEM + 2 * KV_BUF)   // 98304

__device__ __forceinline__ void stage_kv(
    const __nv_bfloat16* __restrict__ Kh, const __nv_bfloat16* __restrict__ Kl,
    const __nv_bfloat16* __restrict__ Vh, const __nv_bfloat16* __restrict__ Vl,
    uint32_t sbase, size_t gbase, int tid)
{
#pragma unroll
    for (int t = 0; t < 4; t++) {
        int i = tid + t * 128;
        int row = i >> 3;
        int c16 = i & 7;
        uint32_t doff = swz8(row, c16);
        size_t goff = gbase + (size_t)row * KVDIM + c16 * 8;
        CP_ASYNC16(sbase + 0     + doff, Kh + goff);
        CP_ASYNC16(sbase + 8192  + doff, Kl + goff);
        CP_ASYNC16(sbase + 16384 + doff, Vh + goff);
        CP_ASYNC16(sbase + 24576 + doff, Vl + goff);
    }
}

__global__ void __launch_bounds__(128) flash_mma(
    const __nv_bfloat16* __restrict__ Qh, const __nv_bfloat16* __restrict__ Ql,
    const __nv_bfloat16* __restrict__ Kh, const __nv_bfloat16* __restrict__ Kl,
    const __nv_bfloat16* __restrict__ Vh, const __nv_bfloat16* __restrict__ Vl,
    __nv_bfloat16* __restrict__ Oh, __nv_bfloat16* __restrict__ Ol)
{
    extern __shared__ char smem[];
    uint32_t sb = smem_u32(smem);
    const int qt = blockIdx.x;
    const int h  = blockIdx.y;
    const int b  = blockIdx.z;
    const int kvh = h / GROUPS;
    const int tid = threadIdx.x;
    const int lane = tid & 31;
    const int w = tid >> 5;
    const int qbase = qt * 128;

#pragma unroll
    for (int t = 0; t < 8; t++) {
        int i = tid + t * 128;
        int row = i >> 3;
        int c16 = i & 7;
        uint32_t doff = swz8(row, c16);
        size_t goff = (size_t)(b * SEQ + qbase + row) * DMODEL + h * HDIM + c16 * 8;
        CP_ASYNC16(sb + doff, Qh + goff);
        CP_ASYNC16(sb + 16384 + doff, Ql + goff);
    }
    size_t kvg0 = (size_t)(b * SEQ) * KVDIM + kvh * HDIM;
    stage_kv(Kh, Kl, Vh, Vl, sb + FQ_SMEM, kvg0, tid);
    CP_COMMIT();

    float acc[2][8][4];
#pragma unroll
    for (int mt = 0; mt < 2; mt++)
#pragma unroll
        for (int nt = 0; nt < 8; nt++)
#pragma unroll
            for (int e = 0; e < 4; e++) acc[mt][nt][e] = 0.f;
    float mrow[2][2] = {{-CUDART_INF_F, -CUDART_INF_F},
                        {-CUDART_INF_F, -CUDART_INF_F}};
    float lrow[2][2] = {{0.f, 0.f}, {0.f, 0.f}};

    const int nb = 2 * qt + 2;
    for (int c = 0; c < nb; c++) {
        if (c + 1 < nb) {
            stage_kv(Kh, Kl, Vh, Vl, sb + FQ_SMEM + ((c + 1) & 1) * KV_BUF,
                     kvg0 + (size_t)(c + 1) * 64 * KVDIM, tid);
            CP_COMMIT();
            CP_WAIT1();
        } else {
            CP_WAIT0();
        }
        __syncthreads();

        uint32_t sk = sb + FQ_SMEM + (c & 1) * KV_BUF;

        float S[2][8][4];
#pragma unroll
        for (int mt = 0; mt < 2; mt++)
#pragma unroll
            for (int nt = 0; nt < 8; nt++)
#pragma unroll
                for (int e = 0; e < 4; e++) S[mt][nt][e] = 0.f;

#pragma unroll
        for (int ks = 0; ks < 4; ks++) {
            uint32_t qh[2][4], ql[2][4];
#pragma unroll
            for (int mt = 0; mt < 2; mt++) {
                int row = w * 32 + mt * 16 + (lane & 15);
                int c16 = ks * 2 + (lane >> 4);
                uint32_t off = swz8(row, c16);
                LDMATRIX_X4(qh[mt][0], qh[mt][1], qh[mt][2], qh[mt][3], sb + off);
                LDMATRIX_X4(ql[mt][0], ql[mt][1], ql[mt][2], ql[mt][3],
                            sb + 16384 + off);
            }
#pragma unroll
            for (int np = 0; np < 4; np++) {
                int row = np * 16 + ((lane >> 4) * 8) + (lane & 7);
                int c16 = ks * 2 + ((lane >> 3) & 1);
                uint32_t off = swz8(row, c16);
                uint32_t kh[4], kl[4];
                LDMATRIX_X4(kh[0], kh[1], kh[2], kh[3], sk + off);
                LDMATRIX_X4(kl[0], kl[1], kl[2], kl[3], sk + 8192 + off);
#pragma unroll
                for (int mt = 0; mt < 2; mt++) {
                    MMA16816(S[mt][2 * np],     qh[mt], (kh + 0));
                    MMA16816(S[mt][2 * np + 1], qh[mt], (kh + 2));
                    MMA16816(S[mt][2 * np],     qh[mt], (kl + 0));
                    MMA16816(S[mt][2 * np + 1], qh[mt], (kl + 2));
                    MMA16816(S[mt][2 * np],     ql[mt], (kh + 0));
                    MMA16816(S[mt][2 * np + 1], ql[mt], (kh + 2));
                }
            }
        }

        if (c >= 2 * qt) {
            int kb = c * 64;
#pragma unroll
            for (int mt = 0; mt < 2; mt++) {
                int r0 = qbase + w * 32 + mt * 16 + (lane >> 2);
#pragma unroll
                for (int nt = 0; nt < 8; nt++) {
                    int key = kb + nt * 8 + (lane & 3) * 2;
                    if (key > r0)     S[mt][nt][0] = -CUDART_INF_F;
                    if (key + 1 > r0) S[mt][nt][1] = -CUDART_INF_F;
                    if (key > r0 + 8)     S[mt][nt][2] = -CUDART_INF_F;
                    if (key + 1 > r0 + 8) S[mt][nt][3] = -CUDART_INF_F;
                }
            }
        }

        uint32_t aPh[2][4][4], aPl[2][4][4];
#pragma unroll
        for (int mt = 0; mt < 2; mt++) {
#pragma unroll
            for (int e2 = 0; e2 < 2; e2++) {
                float mx = -CUDART_INF_F;
#pragma unroll
                for (int nt = 0; nt < 8; nt++)
                    mx = fmaxf(mx, fmaxf(S[mt][nt][2 * e2], S[mt][nt][2 * e2 + 1]));
                mx = fmaxf(mx, __shfl_xor_sync(0xffffffffu, mx, 1));
                mx = fmaxf(mx, __shfl_xor_sync(0xffffffffu, mx, 2));
                float mn = fmaxf(mrow[mt][e2], mx);
                float alpha = __expf(mrow[mt][e2] - mn);
                mrow[mt][e2] = mn;
                float sum = 0.f;
#pragma unroll
                for (int nt = 0; nt < 8; nt++) {
                    float p0 = __expf(S[mt][nt][2 * e2] - mn);
                    float p1 = __expf(S[mt][nt][2 * e2 + 1] - mn);
                    S[mt][nt][2 * e2] = p0;
                    S[mt][nt][2 * e2 + 1] = p1;
                    sum += p0 + p1;
                }
                sum += __shfl_xor_sync(0xffffffffu, sum, 1);
                sum += __shfl_xor_sync(0xffffffffu, sum, 2);
                lrow[mt][e2] = lrow[mt][e2] * alpha + sum;
#pragma unroll
                for (int nt = 0; nt < 8; nt++) {
                    acc[mt][nt][2 * e2] *= alpha;
                    acc[mt][nt][2 * e2 + 1] *= alpha;
                }
            }
#pragma unroll
            for (int kc = 0; kc < 4; kc++) {
#pragma unroll
                for (int r = 0; r < 4; r++) {
                    int nt = 2 * kc + (r >> 1);
                    int e0 = (r & 1) * 2;
                    float p0 = S[mt][nt][e0], p1 = S[mt][nt][e0 + 1];
                    __nv_bfloat162 hh = __floats2bfloat162_rn(p0, p1);
                    float r0 = p0 - __bfloat162float(hh.x);
                    float r1 = p1 - __bfloat162float(hh.y);
                    __nv_bfloat162 ll = __floats2bfloat162_rn(r0, r1);
                    aPh[mt][kc][r] = *reinterpret_cast<uint32_t*>(&hh);
                    aPl[mt][kc][r] = *reinterpret_cast<uint32_t*>(&ll);
                }
            }
        }

#pragma unroll
        for (int kc = 0; kc < 4; kc++) {
#pragma unroll
            for (int dp = 0; dp < 4; dp++) {
                int row = kc * 16 + ((lane >> 3) & 1) * 8 + (lane & 7);
                int c16 = dp * 2 + (lane >> 4);
                uint32_t off = swz8(row, c16);
                uint32_t vh[4], vl[4];
                LDMATRIX_X4T(vh[0], vh[1], vh[2], vh[3], sk + 16384 + off);
                LDMATRIX_X4T(vl[0], vl[1], vl[2], vl[3], sk + 24576 + off);
#pragma unroll
                for (int mt = 0; mt < 2; mt++) {
                    MMA16816(acc[mt][2 * dp],     aPh[mt][kc], (vh + 0));
                    MMA16816(acc[mt][2 * dp + 1], aPh[mt][kc], (vh + 2));
                    MMA16816(acc[mt][2 * dp],     aPh[mt][kc], (vl + 0));
                    MMA16816(acc[mt][2 * dp + 1], aPh[mt][kc], (vl + 2));
                    MMA16816(acc[mt][2 * dp],     aPl[mt][kc], (vh + 0));
                    MMA16816(acc[mt][2 * dp + 1], aPl[mt][kc], (vh + 2));
                }
            }
        }
        __syncthreads();
    }

    // epilogue: O/l -> bf16 hi/lo (directly consumable by the Wo GEMM)
#pragma unroll
    for (int mt = 0; mt < 2; mt++) {
        float inv0 = 1.0f / lrow[mt][0];
        float inv1 = 1.0f / lrow[mt][1];
        int r0 = qbase + w * 32 + mt * 16 + (lane >> 2);
        size_t t0 = (size_t)(b * SEQ + r0) * DMODEL + h * HDIM;
        size_t t1 = t0 + 8 * DMODEL;
#pragma unroll
        for (int nt = 0; nt < 8; nt++) {
            int d = nt * 8 + (lane & 3) * 2;
            float v0 = acc[mt][nt][0] * inv0, v1 = acc[mt][nt][1] * inv0;
            float v2 = acc[mt][nt][2] * inv1, v3 = acc[mt][nt][3] * inv1;
            __nv_bfloat162 h01 = __floats2bfloat162_rn(v0, v1);
            __nv_bfloat162 h23 = __floats2bfloat162_rn(v2, v3);
            __nv_bfloat162 l01 = __floats2bfloat162_rn(
                v0 - __bfloat162float(h01.x), v1 - __bfloat162float(h01.y));
            __nv_bfloat162 l23 = __floats2bfloat162_rn(
                v2 - __bfloat162float(h23.x), v3 - __bfloat162float(h23.y));
            *reinterpret_cast<__nv_bfloat162*>(Oh + t0 + d) = h01;
            *reinterpret_cast<__nv_bfloat162*>(Oh + t1 + d) = h23;
            *reinterpret_cast<__nv_bfloat162*>(Ol + t0 + d) = l01;
            *reinterpret_cast<__nv_bfloat162*>(Ol + t1 + d) = l23;
        }
    }
}

// ---------------- launch ----------------------------------------------------
extern "C" void kernel_launch(void* const* d_in, const int* in_sizes, int n_in,
                              void* d_out, int out_size)
{
    const float* hidden = (const float*)d_in[0];
    const float* cs     = (const float*)d_in[1];
    const float* sn     = (const float*)d_in[2];
    const float* Wq     = (const float*)d_in[3];
    const float* Wk     = (const float*)d_in[4];
    const float* Wv     = (const float*)d_in[5];
    const float* Wo     = (const float*)d_in[6];
    float* out          = (float*)d_out;

    float* QKV = nullptr; cudaGetSymbolAddress((void**)&QKV, g_QKV);
    __nv_bfloat16* Ah = nullptr; cudaGetSymbolAddress((void**)&Ah, g_Ahi);
    __nv_bfloat16* Al = nullptr; cudaGetSymbolAddress((void**)&Al, g_Alo);
    __nv_bfloat16* Bh = nullptr; cudaGetSymbolAddress((void**)&Bh, g_Bhi);
    __nv_bfloat16* Bl = nullptr; cudaGetSymbolAddress((void**)&Bl, g_Blo);
    __nv_bfloat16* Qh = nullptr; cudaGetSymbolAddress((void**)&Qh, g_Qh);
    __nv_bfloat16* Ql = nullptr; cudaGetSymbolAddress((void**)&Ql, g_Ql);
    __nv_bfloat16* Kh = nullptr; cudaGetSymbolAddress((void**)&Kh, g_Kh);
    __nv_bfloat16* Kl = nullptr; cudaGetSymbolAddress((void**)&Kl, g_Kl);
    __nv_bfloat16* Vh = nullptr; cudaGetSymbolAddress((void**)&Vh, g_Vh);
    __nv_bfloat16* Vl = nullptr; cudaGetSymbolAddress((void**)&Vl, g_Vl);

    static bool attr_set = false;
    if (!attr_set) {
        cudaFuncSetAttribute(gemm_mma, cudaFuncAttributeMaxDynamicSharedMemorySize,
                             GEMM_SMEM);
        cudaFuncSetAttribute(flash_mma, cudaFuncAttributeMaxDynamicSharedMemorySize,
                             FLASH_SMEM);
        attr_set = true;
    }

    const int n4 = TOK * DMODEL / 4;

    // hidden -> bf16 hi/lo (A operand)
    split_kernel<<<n4 / 256, 256>>>(hidden, (__nv_bfloat162*)Ah,
                                    (__nv_bfloat162*)Al, n4);

    // B = [WqT ; WkT ; WvT] -> fused QKV GEMM
    transpose_split<<<dim3(DMODEL / 32, DMODEL / 32), dim3(32, 8)>>>(Wq, Bh, Bl, DMODEL, 0);
    transpose_split<<<dim3(KVDIM / 32, DMODEL / 32), dim3(32, 8)>>>(Wk, Bh, Bl, KVDIM, DMODEL);
    transpose_split<<<dim3(KVDIM / 32, DMODEL / 32), dim3(32, 8)>>>(Wv, Bh, Bl, KVDIM, DMODEL + KVDIM);
    gemm_mma<<<dim3(QKVN / BN, TOK / BM), 256, GEMM_SMEM>>>(Ah, Al, Bh, Bl, QKV, QKVN);

    // RoPE + split (strided reads from fused QKV)
    {
        int totq = TOK * NHEADS * 32;
        rope_split<<<(totq + 255) / 256, 256>>>(QKV, QKVN, 0, cs, sn, Qh, Ql,
                                                NHEADS, ATTN_SCALE);
        int totk = TOK * NKV * 32;
        rope_split<<<(totk + 255) / 256, 256>>>(QKV, QKVN, DMODEL, cs, sn, Kh, Kl,
                                                NKV, 1.0f);
        int nv = TOK * KVDIM / 4;
        split_strided<<<(nv + 255) / 256, 256>>>(QKV, QKVN, DMODEL + KVDIM,
                                                 (__nv_bfloat162*)Vh,
                                                 (__nv_bfloat162*)Vl, KVDIM);
    }

    // Wo transpose (Bh/Bl free after QKV GEMM)
    transpose_split<<<dim3(DMODEL / 32, DMODEL / 32), dim3(32, 8)>>>(Wo, Bh, Bl, DMODEL, 0);

    // flash attention -> writes bf16 hi/lo straight into the Wo-GEMM A buffers
    {
        dim3 grid(SEQ / 128, NHEADS, BSZ);
        flash_mma<<<grid, 128, FLASH_SMEM>>>(Qh, Ql, Kh, Kl, Vh, Vl, Ah, Al);
    }

    // out = attn @ Wo
    gemm_mma<<<dim3(DMODEL / BN, TOK / BM), 256, GEMM_SMEM>>>(Ah, Al, Bh, Bl, out, DMODEL);
}